// round 7
// baseline (speedup 1.0000x reference)
#include <cuda_runtime.h>
#include <cuda_fp16.h>
#include <cstdint>

#define BSZ 256
#define HID 4096
#define NIN 1024
#define NOUT 10
#define STEPS_TOTAL 25
#define STEPS_FREE 20

// GEMM tiling: BM=128, BN=64, BK=64 halfs per iter, 128 threads (4 warps)
#define BKK 64
#define NSTAGE 3
#define ROWH 72                              // smem row stride in halfs (144 B)
#define STAGE_HALFS ((128 + 64) * ROWH)      // A(128 rows) + B(64 rows)
#define SMEM_BYTES (NSTAGE * STAGE_HALFS * 2)  // 82944 B -> 2 CTAs/SM

// ---------------- persistent device scratch ----------------
__device__ __align__(128) __half g_rx[BSZ * NIN];
__device__ __align__(128) float  g_c0[BSZ * HID];
__device__ __align__(128) __half g_c0q[BSZ * HID];      // 0.25*c0, fp16
__device__ __align__(128) __half g_s1[2][BSZ * HID];
__device__ __align__(128) __half g_s2[2][BSZ * HID];
__device__ __align__(128) float  g_s3[2][BSZ * NOUT];
__device__ __align__(128) __half g_fw0T[(size_t)HID * NIN];
__device__ __align__(128) __half g_fw1T[(size_t)HID * HID];
__device__ __align__(128) __half g_bw1T[(size_t)HID * HID];

// ---------------- helpers ----------------
__device__ __forceinline__ uint32_t smem_u32(const void* p) {
    uint32_t a;
    asm("{ .reg .u64 t; cvta.to.shared.u64 t, %1; cvt.u32.u64 %0, t; }"
        : "=r"(a) : "l"(p));
    return a;
}

__device__ __forceinline__ void cp16(uint32_t dst, const void* src) {
    asm volatile("cp.async.cg.shared.global [%0], [%1], 16;"
                 :: "r"(dst), "l"(src) : "memory");
}
#define CP_COMMIT() asm volatile("cp.async.commit_group;" ::: "memory")
#define CP_WAIT(n)  asm volatile("cp.async.wait_group %0;" :: "n"(n) : "memory")

__device__ __forceinline__ void ldsm4(uint32_t& r0, uint32_t& r1,
                                      uint32_t& r2, uint32_t& r3, uint32_t addr) {
    asm volatile("ldmatrix.sync.aligned.m8n8.x4.shared.b16 {%0,%1,%2,%3}, [%4];"
                 : "=r"(r0), "=r"(r1), "=r"(r2), "=r"(r3) : "r"(addr));
}

// m16n8k16 fp16 mma, fp32 accum
__device__ __forceinline__ void mma_f16(float* c, const uint32_t* a,
                                        uint32_t b0, uint32_t b1) {
    asm volatile(
        "mma.sync.aligned.m16n8k16.row.col.f32.f16.f16.f32 "
        "{%0,%1,%2,%3}, {%4,%5,%6,%7}, {%8,%9}, {%0,%1,%2,%3};"
        : "+f"(c[0]), "+f"(c[1]), "+f"(c[2]), "+f"(c[3])
        : "r"(a[0]), "r"(a[1]), "r"(a[2]), "r"(a[3]), "r"(b0), "r"(b1));
}

// ---------------- GEMM tile (device) ----------------
// [128,64] tile at (rowBase,colBase) of D[M,4096] = A[M,K] @ BT[4096,K]^T
// 128 threads, 4 warps; warp w computes rows [w*32, w*32+32) x all 64 cols.
// MODE 0: OutF = acc (fp32)                                   (c0)
// MODE 1: OutH = h(clip(0.5*Sold + C0q + 0.25*acc))           (s1; C0q = 0.25*c0)
// MODE 2: OutH = h(clip(0.5*Sold + 0.25*(acc + s3old@bw2)))   (s2)
template <int MODE>
__device__ __forceinline__ void gemm_tile(
    const __half* __restrict__ A, const __half* __restrict__ BT, int K,
    float* __restrict__ OutF, __half* __restrict__ OutH,
    const __half* __restrict__ Sold, const __half* __restrict__ C0q,
    const float* __restrict__ s3old, const float* __restrict__ bw2,
    int rowBase, int colBase, __half* smem)
{
    const int tid  = threadIdx.x;
    const int lane = tid & 31;
    const int wid  = tid >> 5;              // 0..3 == warpM
    const int g = lane >> 2, q = lane & 3;

    float acc[2][8][4];
#pragma unroll
    for (int mi = 0; mi < 2; mi++)
#pragma unroll
        for (int ni = 0; ni < 8; ni++)
#pragma unroll
            for (int t = 0; t < 4; t++) acc[mi][ni][t] = 0.0f;

    // loaders: A -> thread t = row t, 8 segs; B -> row t>>1, 4 segs
    const int brow = tid >> 1;
    const int bseg0 = (tid & 1) * 4;
    const __half* Ag = A  + (size_t)(rowBase + tid) * K;
    const __half* Bg = BT + (size_t)(colBase + brow) * K;

    const int nIt = K / BKK;

#define LOAD_STAGE(s, kt)                                            \
    do {                                                             \
        __half* As_ = smem + (s) * STAGE_HALFS;                      \
        __half* Bs_ = As_ + 128 * ROWH;                              \
        uint32_t dA = smem_u32(As_ + tid * ROWH);                    \
        uint32_t dB = smem_u32(Bs_ + brow * ROWH);                   \
        _Pragma("unroll")                                            \
        for (int u = 0; u < 8; u++)                                  \
            cp16(dA + u * 16, Ag + (kt) + u * 8);                    \
        _Pragma("unroll")                                            \
        for (int u = 0; u < 4; u++) {                                \
            int sg = bseg0 + u;                                      \
            cp16(dB + sg * 16, Bg + (kt) + sg * 8);                  \
        }                                                            \
    } while (0)

    LOAD_STAGE(0, 0);   CP_COMMIT();
    LOAD_STAGE(1, BKK); CP_COMMIT();

    const int lrow = (lane & 7) + ((lane >> 3) & 1) * 8;
    const int lcolB = ((lane >> 4) & 1) * 16;   // bytes

    uint32_t a[2][2][4];   // [buf][mi][frag]
    uint32_t b[2][4][4];   // [buf][nj][frag]

#define LOAD_FRAGS(buf, aB, bB, ko)                                          \
    do {                                                                     \
        _Pragma("unroll")                                                    \
        for (int mi = 0; mi < 2; mi++)                                       \
            ldsm4(a[buf][mi][0], a[buf][mi][1], a[buf][mi][2], a[buf][mi][3],\
                  (aB) + mi * 16 * (ROWH * 2) + (ko));                       \
        _Pragma("unroll")                                                    \
        for (int nj = 0; nj < 4; nj++)                                       \
            ldsm4(b[buf][nj][0], b[buf][nj][1], b[buf][nj][2], b[buf][nj][3],\
                  (bB) + nj * 16 * (ROWH * 2) + (ko));                       \
    } while (0)

#define DO_MMA(buf)                                                          \
    do {                                                                     \
        _Pragma("unroll")                                                    \
        for (int nj = 0; nj < 4; nj++) {                                     \
            _Pragma("unroll")                                                \
            for (int mi = 0; mi < 2; mi++) {                                 \
                mma_f16(acc[mi][nj * 2 + 0], a[buf][mi],                     \
                        b[buf][nj][0], b[buf][nj][2]);                       \
                mma_f16(acc[mi][nj * 2 + 1], a[buf][mi],                     \
                        b[buf][nj][1], b[buf][nj][3]);                       \
            }                                                                \
        }                                                                    \
    } while (0)

    // prime: wait for stage 0, load its first k-step fragments
    CP_WAIT(1);
    __syncthreads();
    {
        const __half* As = smem;
        const __half* Bs = As + 128 * ROWH;
        const uint32_t aB = smem_u32(As + (wid * 32 + lrow) * ROWH) + lcolB;
        const uint32_t bB = smem_u32(Bs + lrow * ROWH) + lcolB;
        LOAD_FRAGS(0, aB, bB, 0);
    }

    for (int it = 0; it < nIt; ++it) {
        if (it + 2 < nIt) {
            LOAD_STAGE((it + 2) % NSTAGE, (it + 2) * BKK);
        }
        CP_COMMIT();

        const __half* As = smem + (it % NSTAGE) * STAGE_HALFS;
        const __half* Bs = As + 128 * ROWH;
        const uint32_t aB = smem_u32(As + (wid * 32 + lrow) * ROWH) + lcolB;
        const uint32_t bB = smem_u32(Bs + lrow * ROWH) + lcolB;

        // k-steps 0..2: prefetch ks+1 into other buffer, then mma current
#pragma unroll
        for (int ks = 0; ks < 3; ks++) {
            LOAD_FRAGS((ks + 1) & 1, aB, bB, (ks + 1) * 32);
            DO_MMA(ks & 1);
        }

        // boundary: wait for next stage, prefetch its first k-step
        if (it + 1 < nIt) {
            CP_WAIT(1);
            __syncthreads();
            const __half* As2 = smem + ((it + 1) % NSTAGE) * STAGE_HALFS;
            const __half* Bs2 = As2 + 128 * ROWH;
            const uint32_t aB2 = smem_u32(As2 + (wid * 32 + lrow) * ROWH) + lcolB;
            const uint32_t bB2 = smem_u32(Bs2 + lrow * ROWH) + lcolB;
            LOAD_FRAGS(0, aB2, bB2, 0);
        }
        DO_MMA(1);   // k-step 3 lives in buffer 1
    }
#undef LOAD_FRAGS
#undef DO_MMA
#undef LOAD_STAGE

    // ---------------- epilogue ----------------
    const int rw = rowBase + wid * 32;
    const int cw = colBase;

    if (MODE == 2) {
        float s3r[2][2][10];
#pragma unroll
        for (int mi = 0; mi < 2; mi++)
#pragma unroll
            for (int h = 0; h < 2; h++) {
                const int r = rw + mi * 16 + h * 8 + g;
#pragma unroll
                for (int k = 0; k < NOUT; k++)
                    s3r[mi][h][k] = s3old[r * NOUT + k];
            }
#pragma unroll
        for (int ni = 0; ni < 8; ni++) {
            const int cb = cw + ni * 8 + q * 2;
#pragma unroll
            for (int k = 0; k < NOUT; k++) {
                const float2 b2 = *(const float2*)&bw2[(size_t)k * HID + cb];
#pragma unroll
                for (int mi = 0; mi < 2; mi++) {
                    acc[mi][ni][0] = fmaf(s3r[mi][0][k], b2.x, acc[mi][ni][0]);
                    acc[mi][ni][1] = fmaf(s3r[mi][0][k], b2.y, acc[mi][ni][1]);
                    acc[mi][ni][2] = fmaf(s3r[mi][1][k], b2.x, acc[mi][ni][2]);
                    acc[mi][ni][3] = fmaf(s3r[mi][1][k], b2.y, acc[mi][ni][3]);
                }
            }
        }
    }

#pragma unroll
    for (int mi = 0; mi < 2; mi++) {
#pragma unroll
        for (int ni = 0; ni < 8; ni++) {
            const int r0 = rw + mi * 16 + g;
            const int cb = cw + ni * 8 + q * 2;
#pragma unroll
            for (int h = 0; h < 2; h++) {
                const size_t idx = (size_t)(r0 + h * 8) * HID + cb;
                float vx = acc[mi][ni][h * 2 + 0];
                float vy = acc[mi][ni][h * 2 + 1];
                if (MODE == 0) {
                    *(float2*)&OutF[idx] = make_float2(vx, vy);
                } else {
                    const float2 so = __half22float2(*(const __half2*)&Sold[idx]);
                    if (MODE == 1) {
                        const float2 c2 = __half22float2(*(const __half2*)&C0q[idx]);
                        vx = 0.5f * so.x + c2.x + 0.25f * vx;
                        vy = 0.5f * so.y + c2.y + 0.25f * vy;
                    } else {
                        vx = 0.5f * so.x + 0.25f * vx;
                        vy = 0.5f * so.y + 0.25f * vy;
                    }
                    vx = fminf(fmaxf(vx, 0.0f), 1.0f);
                    vy = fminf(fmaxf(vy, 0.0f), 1.0f);
                    *(__half2*)&OutH[idx] = __floats2half2_rn(vx, vy);
                }
            }
        }
    }
}

// ---------------- s3 tile (device): 32 rows, 128 threads ----------------
__device__ __forceinline__ void s3_tile(
    const __half* __restrict__ s2old, const float* __restrict__ fw2,
    const float* __restrict__ s3old, const float* __restrict__ y,
    float* __restrict__ s3new, int weak, int rowBase, __half* smem_raw)
{
    const int tid = threadIdx.x, lane = tid & 31, wid = tid >> 5;
    float* fs = (float*)smem_raw;   // [512][11] floats = 22.5 KB (< SMEM_BYTES)
    float acc[8][NOUT];
#pragma unroll
    for (int r = 0; r < 8; r++)
#pragma unroll
        for (int j = 0; j < NOUT; j++) acc[r][j] = 0.0f;

    for (int c = 0; c < 8; c++) {
        __syncthreads();
        for (int i = tid; i < 512 * NOUT; i += 128) {
            int kl = i / NOUT, j = i - kl * NOUT;
            fs[kl * 11 + j] = fw2[(size_t)(c * 512 + kl) * NOUT + j];
        }
        __syncthreads();
#pragma unroll
        for (int r = 0; r < 8; r++) {
            const int row = rowBase + wid * 8 + r;
            const __half* s2r = s2old + (size_t)row * HID + c * 512;
#pragma unroll 4
            for (int i = 0; i < 16; i++) {
                const int kl = lane + i * 32;
                const float sv = __half2float(s2r[kl]);
#pragma unroll
                for (int j = 0; j < NOUT; j++)
                    acc[r][j] = fmaf(sv, fs[kl * 11 + j], acc[r][j]);
            }
        }
    }

#pragma unroll
    for (int r = 0; r < 8; r++) {
        const int row = rowBase + wid * 8 + r;
#pragma unroll
        for (int j = 0; j < NOUT; j++) {
            float v = acc[r][j];
#pragma unroll
            for (int o = 16; o; o >>= 1) v += __shfl_xor_sync(0xffffffffu, v, o);
            if (lane == 0) {
                float out = weak ? 0.5f * (v + y[row * NOUT + j])
                                 : 0.5f * (s3old[row * NOUT + j] + v);
                s3new[row * NOUT + j] = fminf(fmaxf(out, 0.0f), 1.0f);
            }
        }
    }
}

// ---------------- fused step kernel: 264 CTAs (~2/SM) ----------------
__global__ __launch_bounds__(128, 2) void step_kernel(
    const __half* __restrict__ s1old, const __half* __restrict__ s2old,
    const float* __restrict__ s3old,
    __half* __restrict__ s1new, __half* __restrict__ s2new, float* __restrict__ s3new,
    const __half* __restrict__ fw1T, const __half* __restrict__ bw1T,
    const float* __restrict__ bw2, const float* __restrict__ fw2,
    const __half* __restrict__ c0q, const float* __restrict__ y, int weak)
{
    extern __shared__ __half smem[];
    const int bid = blockIdx.x;
    if (bid < 128) {
        gemm_tile<1>(s2old, bw1T, HID, nullptr, s1new, s1old, c0q, nullptr, nullptr,
                     (bid >> 6) * 128, (bid & 63) * 64, smem);
    } else if (bid < 256) {
        const int t = bid - 128;
        gemm_tile<2>(s1old, fw1T, HID, nullptr, s2new, s2old, nullptr, s3old, bw2,
                     (t >> 6) * 128, (t & 63) * 64, smem);
    } else {
        s3_tile(s2old, fw2, s3old, y, s3new, weak, (bid - 256) * 32, smem);
    }
}

__global__ __launch_bounds__(128, 2) void c0_kernel(
    const __half* __restrict__ rx, const __half* __restrict__ fw0T,
    float* __restrict__ c0)
{
    extern __shared__ __half smem[];
    const int bid = blockIdx.x;
    gemm_tile<0>(rx, fw0T, NIN, c0, nullptr, nullptr, nullptr, nullptr, nullptr,
                 (bid >> 6) * 128, (bid & 63) * 64, smem);
}

// ---------------- small kernels ----------------
__global__ void clip_kernel(const float* __restrict__ x, __half* __restrict__ rx, int n) {
    int i = blockIdx.x * blockDim.x + threadIdx.x;
    if (i < n) rx[i] = __float2half_rn(fminf(fmaxf(x[i], 0.0f), 1.0f));
}

__global__ void init_kernel(const float* __restrict__ c0, __half* __restrict__ c0q,
                            __half* __restrict__ s1, __half* __restrict__ s2,
                            float* __restrict__ s3) {
    int i = blockIdx.x * blockDim.x + threadIdx.x;
    if (i < BSZ * HID) {
        float qc = 0.25f * c0[i];
        c0q[i] = __float2half_rn(qc);
        s1[i] = __float2half_rn(fminf(fmaxf(qc, 0.0f), 1.0f));
        s2[i] = __half(0.0f);
    }
    if (i < BSZ * NOUT) s3[i] = 0.0f;
}

__global__ void transpose_kernel(const float* __restrict__ src, __half* __restrict__ dst,
                                 int R, int C) {
    __shared__ float tile[32][33];
    int bx = blockIdx.x * 32, by = blockIdx.y * 32;
    int x = bx + threadIdx.x;
    int y = by + threadIdx.y;
#pragma unroll
    for (int i = 0; i < 32; i += 8)
        tile[threadIdx.y + i][threadIdx.x] = src[(size_t)(y + i) * C + x];
    __syncthreads();
    x = by + threadIdx.x;
    y = bx + threadIdx.y;
#pragma unroll
    for (int i = 0; i < 32; i += 8)
        dst[(size_t)(y + i) * R + x] = __float2half_rn(tile[threadIdx.x][threadIdx.y + i]);
}

__global__ void concat_kernel(const __half* __restrict__ s1,
                              const __half* __restrict__ s2,
                              const float* __restrict__ s3,
                              float* __restrict__ out)
{
    int i = blockIdx.x * blockDim.x + threadIdx.x;
    const int W = HID + HID + NOUT;
    if (i >= BSZ * W) return;
    int row = i / W;
    int c = i - row * W;
    float v;
    if (c < HID)          v = __half2float(s1[(size_t)row * HID + c]);
    else if (c < 2 * HID) v = __half2float(s2[(size_t)row * HID + (c - HID)]);
    else                  v = s3[row * NOUT + (c - 2 * HID)];
    out[i] = v;
}

// ---------------- launch ----------------
extern "C" void kernel_launch(void* const* d_in, const int* in_sizes, int n_in,
                              void* d_out, int out_size)
{
    const float* x   = (const float*)d_in[0];
    const float* fw0 = (const float*)d_in[1];
    const float* fw1 = (const float*)d_in[2];
    const float* fw2 = (const float*)d_in[3];
    // d_in[4] = bw0 (unused by the dynamics)
    const float* bw1 = (const float*)d_in[5];
    const float* bw2 = (const float*)d_in[6];
    const float* y   = (const float*)d_in[7];
    float* out = (float*)d_out;

    cudaFuncSetAttribute(step_kernel, cudaFuncAttributeMaxDynamicSharedMemorySize, SMEM_BYTES);
    cudaFuncSetAttribute(c0_kernel,   cudaFuncAttributeMaxDynamicSharedMemorySize, SMEM_BYTES);

    __half *rx, *c0q, *s1base, *s2base, *fw0T, *fw1T, *bw1T;
    float *c0, *s3base;
    cudaGetSymbolAddress((void**)&rx, g_rx);
    cudaGetSymbolAddress((void**)&c0, g_c0);
    cudaGetSymbolAddress((void**)&c0q, g_c0q);
    cudaGetSymbolAddress((void**)&s1base, g_s1);
    cudaGetSymbolAddress((void**)&s2base, g_s2);
    cudaGetSymbolAddress((void**)&s3base, g_s3);
    cudaGetSymbolAddress((void**)&fw0T, g_fw0T);
    cudaGetSymbolAddress((void**)&fw1T, g_fw1T);
    cudaGetSymbolAddress((void**)&bw1T, g_bw1T);

    __half* s1p[2] = { s1base, s1base + (size_t)BSZ * HID };
    __half* s2p[2] = { s2base, s2base + (size_t)BSZ * HID };
    float*  s3p[2] = { s3base, s3base + (size_t)BSZ * NOUT };

    {
        dim3 blk(32, 8);
        transpose_kernel<<<dim3(HID / 32, NIN / 32), blk>>>(fw0, fw0T, NIN, HID);
        transpose_kernel<<<dim3(HID / 32, HID / 32), blk>>>(fw1, fw1T, HID, HID);
        transpose_kernel<<<dim3(HID / 32, HID / 32), blk>>>(bw1, bw1T, HID, HID);
    }

    clip_kernel<<<(BSZ * NIN + 255) / 256, 256>>>(x, rx, BSZ * NIN);

    // c0 = rx @ fw0 (loop-invariant), fp32 output
    c0_kernel<<<128, 128, SMEM_BYTES>>>(rx, fw0T, c0);

    // step 0 collapses to elementwise (states start at zero)
    init_kernel<<<(BSZ * HID + 255) / 256, 256>>>(c0, c0q, s1p[1], s2p[1], s3p[1]);

    for (int t = 1; t < STEPS_TOTAL; t++) {
        const int p = t & 1;
        const int q = 1 - p;
        const int weak = (t >= STEPS_FREE) ? 1 : 0;
        step_kernel<<<264, 128, SMEM_BYTES>>>(
            s1p[p], s2p[p], s3p[p],
            s1p[q], s2p[q], s3p[q],
            fw1T, bw1T, bw2, fw2, c0q, y, weak);
    }

    const int fin = STEPS_TOTAL & 1;
    concat_kernel<<<(BSZ * (2 * HID + NOUT) + 255) / 256, 256>>>(
        s1p[fin], s2p[fin], s3p[fin], out);
}

// round 8
// speedup vs baseline: 1.2209x; 1.2209x over previous
#include <cuda_runtime.h>
#include <cuda_fp16.h>
#include <cstdint>

#define BSZ 256
#define HID 4096
#define NIN 1024
#define NOUT 10
#define STEPS_TOTAL 25
#define STEPS_FREE 20

// GEMM tiling: BM=BN=128, BK=128 halfs per iter, 256 threads (8 warps)
#define BKK 128
#define NSTAGE 3
#define ROWH 136                           // smem row stride in halfs (272 B)
#define STAGE_HALFS (2 * 128 * ROWH)       // A + B tiles (69632 B)
#define SMEM_BYTES (NSTAGE * STAGE_HALFS * 2)  // 208896 B

// ---------------- persistent device scratch ----------------
__device__ __align__(128) __half g_rx[BSZ * NIN];
__device__ __align__(128) float  g_c0[BSZ * HID];
__device__ __align__(128) __half g_c0q[BSZ * HID];      // 0.25*c0, fp16
__device__ __align__(128) __half g_s1[2][BSZ * HID];
__device__ __align__(128) __half g_s2[2][BSZ * HID];
__device__ __align__(128) float  g_s3[2][BSZ * NOUT];
__device__ __align__(128) __half g_fw0T[(size_t)HID * NIN];
__device__ __align__(128) __half g_fw1T[(size_t)HID * HID];
__device__ __align__(128) __half g_bw1T[(size_t)HID * HID];

// ---------------- helpers ----------------
__device__ __forceinline__ uint32_t smem_u32(const void* p) {
    uint32_t a;
    asm("{ .reg .u64 t; cvta.to.shared.u64 t, %1; cvt.u32.u64 %0, t; }"
        : "=r"(a) : "l"(p));
    return a;
}

__device__ __forceinline__ void cp16(uint32_t dst, const void* src) {
    asm volatile("cp.async.cg.shared.global [%0], [%1], 16;"
                 :: "r"(dst), "l"(src) : "memory");
}
#define CP_COMMIT() asm volatile("cp.async.commit_group;" ::: "memory")
#define CP_WAIT(n)  asm volatile("cp.async.wait_group %0;" :: "n"(n) : "memory")

__device__ __forceinline__ void ldsm4(uint32_t& r0, uint32_t& r1,
                                      uint32_t& r2, uint32_t& r3, uint32_t addr) {
    asm volatile("ldmatrix.sync.aligned.m8n8.x4.shared.b16 {%0,%1,%2,%3}, [%4];"
                 : "=r"(r0), "=r"(r1), "=r"(r2), "=r"(r3) : "r"(addr));
}

// m16n8k16 fp16 mma, fp32 accum
__device__ __forceinline__ void mma_f16(float* c, const uint32_t* a,
                                        uint32_t b0, uint32_t b1) {
    asm volatile(
        "mma.sync.aligned.m16n8k16.row.col.f32.f16.f16.f32 "
        "{%0,%1,%2,%3}, {%4,%5,%6,%7}, {%8,%9}, {%0,%1,%2,%3};"
        : "+f"(c[0]), "+f"(c[1]), "+f"(c[2]), "+f"(c[3])
        : "r"(a[0]), "r"(a[1]), "r"(a[2]), "r"(a[3]), "r"(b0), "r"(b1));
}

// ---------------- GEMM tile (device) ----------------
// [128,128] tile at (rowBase,colBase) of D[M,4096] = A[M,K] @ BT[4096,K]^T
// MODE 0: OutF = acc (fp32)                                   (c0)
// MODE 1: OutH = h(clip(0.5*Sold + C0q + 0.25*acc))           (s1; C0q = 0.25*c0)
// MODE 2: OutH = h(clip(0.5*Sold + 0.25*(acc + s3old@bw2)))   (s2)
template <int MODE>
__device__ __forceinline__ void gemm_tile(
    const __half* __restrict__ A, const __half* __restrict__ BT, int K,
    float* __restrict__ OutF, __half* __restrict__ OutH,
    const __half* __restrict__ Sold, const __half* __restrict__ C0q,
    const float* __restrict__ s3old, const float* __restrict__ bw2,
    int rowBase, int colBase, __half* smem)
{
    const int tid  = threadIdx.x;
    const int lane = tid & 31;
    const int wid  = tid >> 5;
    const int g = lane >> 2, q = lane & 3;
    const int warpM = wid & 3;   // 4 row-groups of 32
    const int warpN = wid >> 2;  // 2 col-groups of 64

    float acc[2][8][4];
#pragma unroll
    for (int mi = 0; mi < 2; mi++)
#pragma unroll
        for (int ni = 0; ni < 8; ni++)
#pragma unroll
            for (int t = 0; t < 4; t++) acc[mi][ni][t] = 0.0f;

    // loaders: thread -> row tid>>1, 8 of 16 16B-segments (256B per row)
    const int ldr  = tid >> 1;
    const int seg0 = (tid & 1) * 8;

    const __half* Ag = A  + (size_t)(rowBase + ldr) * K;
    const __half* Bg = BT + (size_t)(colBase + ldr) * K;

    const int nIt = K / BKK;

#define LOAD_STAGE(s, kt)                                            \
    do {                                                             \
        __half* As_ = smem + (s) * STAGE_HALFS;                      \
        __half* Bs_ = As_ + 128 * ROWH;                              \
        uint32_t dA = smem_u32(As_ + ldr * ROWH);                    \
        uint32_t dB = smem_u32(Bs_ + ldr * ROWH);                    \
        _Pragma("unroll")                                            \
        for (int u = 0; u < 8; u++) {                                \
            int sg = seg0 + u;                                       \
            cp16(dA + sg * 16, Ag + (kt) + sg * 8);                  \
            cp16(dB + sg * 16, Bg + (kt) + sg * 8);                  \
        }                                                            \
    } while (0)

    LOAD_STAGE(0, 0);   CP_COMMIT();
    LOAD_STAGE(1, BKK); CP_COMMIT();

    const int lrow = (lane & 7) + ((lane >> 3) & 1) * 8;
    const int lcolB = ((lane >> 4) & 1) * 16;   // bytes

    uint32_t a[2][2][4];   // [buf][mi][frag]
    uint32_t b[2][4][4];   // [buf][nj][frag]

#define LOAD_FRAGS(buf, aB, bB, ko)                                          \
    do {                                                                     \
        _Pragma("unroll")                                                    \
        for (int mi = 0; mi < 2; mi++)                                       \
            ldsm4(a[buf][mi][0], a[buf][mi][1], a[buf][mi][2], a[buf][mi][3],\
                  (aB) + mi * 16 * (ROWH * 2) + (ko));                       \
        _Pragma("unroll")                                                    \
        for (int nj = 0; nj < 4; nj++)                                       \
            ldsm4(b[buf][nj][0], b[buf][nj][1], b[buf][nj][2], b[buf][nj][3],\
                  (bB) + nj * 16 * (ROWH * 2) + (ko));                       \
    } while (0)

#define DO_MMA(buf)                                                          \
    do {                                                                     \
        _Pragma("unroll")                                                    \
        for (int nj = 0; nj < 4; nj++) {                                     \
            _Pragma("unroll")                                                \
            for (int mi = 0; mi < 2; mi++) {                                 \
                mma_f16(acc[mi][nj * 2 + 0], a[buf][mi],                     \
                        b[buf][nj][0], b[buf][nj][2]);                       \
                mma_f16(acc[mi][nj * 2 + 1], a[buf][mi],                     \
                        b[buf][nj][1], b[buf][nj][3]);                       \
            }                                                                \
        }                                                                    \
    } while (0)

    // prime: wait for stage 0, load its first k-step fragments
    CP_WAIT(1);
    __syncthreads();
    {
        const __half* As = smem;
        const __half* Bs = As + 128 * ROWH;
        const uint32_t aB = smem_u32(As + (warpM * 32 + lrow) * ROWH) + lcolB;
        const uint32_t bB = smem_u32(Bs + (warpN * 64 + lrow) * ROWH) + lcolB;
        LOAD_FRAGS(0, aB, bB, 0);
    }

    for (int it = 0; it < nIt; ++it) {
        // issue loads for stage it+2 (overwrites stage it-1; safe after last barrier)
        if (it + 2 < nIt) {
            LOAD_STAGE((it + 2) % NSTAGE, (it + 2) * BKK);
        }
        CP_COMMIT();

        const __half* As = smem + (it % NSTAGE) * STAGE_HALFS;
        const __half* Bs = As + 128 * ROWH;
        const uint32_t aB = smem_u32(As + (warpM * 32 + lrow) * ROWH) + lcolB;
        const uint32_t bB = smem_u32(Bs + (warpN * 64 + lrow) * ROWH) + lcolB;

        // k-steps 0..6: prefetch ks+1 into other buffer, then mma current
#pragma unroll
        for (int ks = 0; ks < 7; ks++) {
            LOAD_FRAGS((ks + 1) & 1, aB, bB, (ks + 1) * 32);
            DO_MMA(ks & 1);
        }

        // boundary: wait for next stage, prefetch its first k-step
        if (it + 1 < nIt) {
            CP_WAIT(1);
            __syncthreads();
            const __half* As2 = smem + ((it + 1) % NSTAGE) * STAGE_HALFS;
            const __half* Bs2 = As2 + 128 * ROWH;
            const uint32_t aB2 = smem_u32(As2 + (warpM * 32 + lrow) * ROWH) + lcolB;
            const uint32_t bB2 = smem_u32(Bs2 + (warpN * 64 + lrow) * ROWH) + lcolB;
            LOAD_FRAGS(0, aB2, bB2, 0);
        }
        DO_MMA(1);   // k-step 7 lives in buffer 1
    }
#undef LOAD_FRAGS
#undef DO_MMA
#undef LOAD_STAGE

    // ---------------- epilogue ----------------
    const int rw = rowBase + warpM * 32;
    const int cw = colBase + warpN * 64;

    if (MODE == 2) {
        float s3r[2][2][10];
#pragma unroll
        for (int mi = 0; mi < 2; mi++)
#pragma unroll
            for (int h = 0; h < 2; h++) {
                const int r = rw + mi * 16 + h * 8 + g;
#pragma unroll
                for (int k = 0; k < NOUT; k++)
                    s3r[mi][h][k] = s3old[r * NOUT + k];
            }
#pragma unroll
        for (int ni = 0; ni < 8; ni++) {
            const int cb = cw + ni * 8 + q * 2;
#pragma unroll
            for (int k = 0; k < NOUT; k++) {
                const float2 b2 = *(const float2*)&bw2[(size_t)k * HID + cb];
#pragma unroll
                for (int mi = 0; mi < 2; mi++) {
                    acc[mi][ni][0] = fmaf(s3r[mi][0][k], b2.x, acc[mi][ni][0]);
                    acc[mi][ni][1] = fmaf(s3r[mi][0][k], b2.y, acc[mi][ni][1]);
                    acc[mi][ni][2] = fmaf(s3r[mi][1][k], b2.x, acc[mi][ni][2]);
                    acc[mi][ni][3] = fmaf(s3r[mi][1][k], b2.y, acc[mi][ni][3]);
                }
            }
        }
    }

#pragma unroll
    for (int mi = 0; mi < 2; mi++) {
#pragma unroll
        for (int ni = 0; ni < 8; ni++) {
            const int r0 = rw + mi * 16 + g;
            const int cb = cw + ni * 8 + q * 2;
#pragma unroll
            for (int h = 0; h < 2; h++) {
                const size_t idx = (size_t)(r0 + h * 8) * HID + cb;
                float vx = acc[mi][ni][h * 2 + 0];
                float vy = acc[mi][ni][h * 2 + 1];
                if (MODE == 0) {
                    *(float2*)&OutF[idx] = make_float2(vx, vy);
                } else {
                    const float2 so = __half22float2(*(const __half2*)&Sold[idx]);
                    if (MODE == 1) {
                        const float2 c2 = __half22float2(*(const __half2*)&C0q[idx]);
                        vx = 0.5f * so.x + c2.x + 0.25f * vx;
                        vy = 0.5f * so.y + c2.y + 0.25f * vy;
                    } else {
                        vx = 0.5f * so.x + 0.25f * vx;
                        vy = 0.5f * so.y + 0.25f * vy;
                    }
                    vx = fminf(fmaxf(vx, 0.0f), 1.0f);
                    vy = fminf(fmaxf(vy, 0.0f), 1.0f);
                    *(__half2*)&OutH[idx] = __floats2half2_rn(vx, vy);
                }
            }
        }
    }
}

// ---------------- s3 tile (device): 32 rows, p3 = s2old @ fw2 ----------------
__device__ __forceinline__ void s3_tile(
    const __half* __restrict__ s2old, const float* __restrict__ fw2,
    const float* __restrict__ s3old, const float* __restrict__ y,
    float* __restrict__ s3new, int weak, int rowBase, __half* smem_raw)
{
    const int tid = threadIdx.x, lane = tid & 31, wid = tid >> 5;
    float* fs = (float*)smem_raw;
    float acc[4][NOUT];
#pragma unroll
    for (int r = 0; r < 4; r++)
#pragma unroll
        for (int j = 0; j < NOUT; j++) acc[r][j] = 0.0f;

    for (int c = 0; c < 8; c++) {
        __syncthreads();
        for (int i = tid; i < 512 * NOUT; i += 256) {
            int kl = i / NOUT, j = i - kl * NOUT;
            fs[kl * 11 + j] = fw2[(size_t)(c * 512 + kl) * NOUT + j];
        }
        __syncthreads();
#pragma unroll
        for (int r = 0; r < 4; r++) {
            const int row = rowBase + wid * 4 + r;
            const __half* s2r = s2old + (size_t)row * HID + c * 512;
#pragma unroll 4
            for (int i = 0; i < 16; i++) {
                const int kl = lane + i * 32;
                const float sv = __half2float(s2r[kl]);
#pragma unroll
                for (int j = 0; j < NOUT; j++)
                    acc[r][j] = fmaf(sv, fs[kl * 11 + j], acc[r][j]);
            }
        }
    }

#pragma unroll
    for (int r = 0; r < 4; r++) {
        const int row = rowBase + wid * 4 + r;
#pragma unroll
        for (int j = 0; j < NOUT; j++) {
            float v = acc[r][j];
#pragma unroll
            for (int o = 16; o; o >>= 1) v += __shfl_xor_sync(0xffffffffu, v, o);
            if (lane == 0) {
                float out = weak ? 0.5f * (v + y[row * NOUT + j])
                                 : 0.5f * (s3old[row * NOUT + j] + v);
                s3new[row * NOUT + j] = fminf(fmaxf(out, 0.0f), 1.0f);
            }
        }
    }
}

// ---------------- fused step kernel: 136 CTAs = one wave ----------------
__global__ __launch_bounds__(256, 1) void step_kernel(
    const __half* __restrict__ s1old, const __half* __restrict__ s2old,
    const float* __restrict__ s3old,
    __half* __restrict__ s1new, __half* __restrict__ s2new, float* __restrict__ s3new,
    const __half* __restrict__ fw1T, const __half* __restrict__ bw1T,
    const float* __restrict__ bw2, const float* __restrict__ fw2,
    const __half* __restrict__ c0q, const float* __restrict__ y, int weak)
{
    extern __shared__ __half smem[];
    const int bid = blockIdx.x;
    if (bid < 64) {
        gemm_tile<1>(s2old, bw1T, HID, nullptr, s1new, s1old, c0q, nullptr, nullptr,
                     (bid >> 5) * 128, (bid & 31) * 128, smem);
    } else if (bid < 128) {
        const int t = bid - 64;
        gemm_tile<2>(s1old, fw1T, HID, nullptr, s2new, s2old, nullptr, s3old, bw2,
                     (t >> 5) * 128, (t & 31) * 128, smem);
    } else {
        s3_tile(s2old, fw2, s3old, y, s3new, weak, (bid - 128) * 32, smem);
    }
}

__global__ __launch_bounds__(256, 1) void c0_kernel(
    const __half* __restrict__ rx, const __half* __restrict__ fw0T,
    float* __restrict__ c0)
{
    extern __shared__ __half smem[];
    const int bid = blockIdx.x;
    gemm_tile<0>(rx, fw0T, NIN, c0, nullptr, nullptr, nullptr, nullptr, nullptr,
                 (bid >> 5) * 128, (bid & 31) * 128, smem);
}

// ---------------- small kernels ----------------
__global__ void clip_kernel(const float* __restrict__ x, __half* __restrict__ rx, int n) {
    int i = blockIdx.x * blockDim.x + threadIdx.x;
    if (i < n) rx[i] = __float2half_rn(fminf(fmaxf(x[i], 0.0f), 1.0f));
}

__global__ void init_kernel(const float* __restrict__ c0, __half* __restrict__ c0q,
                            __half* __restrict__ s1, __half* __restrict__ s2,
                            float* __restrict__ s3) {
    int i = blockIdx.x * blockDim.x + threadIdx.x;
    if (i < BSZ * HID) {
        float qc = 0.25f * c0[i];
        c0q[i] = __float2half_rn(qc);
        s1[i] = __float2half_rn(fminf(fmaxf(qc, 0.0f), 1.0f));
        s2[i] = __half(0.0f);
    }
    if (i < BSZ * NOUT) s3[i] = 0.0f;
}

__global__ void transpose_kernel(const float* __restrict__ src, __half* __restrict__ dst,
                                 int R, int C) {
    __shared__ float tile[32][33];
    int bx = blockIdx.x * 32, by = blockIdx.y * 32;
    int x = bx + threadIdx.x;
    int y = by + threadIdx.y;
#pragma unroll
    for (int i = 0; i < 32; i += 8)
        tile[threadIdx.y + i][threadIdx.x] = src[(size_t)(y + i) * C + x];
    __syncthreads();
    x = by + threadIdx.x;
    y = bx + threadIdx.y;
#pragma unroll
    for (int i = 0; i < 32; i += 8)
        dst[(size_t)(y + i) * R + x] = __float2half_rn(tile[threadIdx.x][threadIdx.y + i]);
}

__global__ void concat_kernel(const __half* __restrict__ s1,
                              const __half* __restrict__ s2,
                              const float* __restrict__ s3,
                              float* __restrict__ out)
{
    int i = blockIdx.x * blockDim.x + threadIdx.x;
    const int W = HID + HID + NOUT;
    if (i >= BSZ * W) return;
    int row = i / W;
    int c = i - row * W;
    float v;
    if (c < HID)          v = __half2float(s1[(size_t)row * HID + c]);
    else if (c < 2 * HID) v = __half2float(s2[(size_t)row * HID + (c - HID)]);
    else                  v = s3[row * NOUT + (c - 2 * HID)];
    out[i] = v;
}

// ---------------- launch ----------------
extern "C" void kernel_launch(void* const* d_in, const int* in_sizes, int n_in,
                              void* d_out, int out_size)
{
    const float* x   = (const float*)d_in[0];
    const float* fw0 = (const float*)d_in[1];
    const float* fw1 = (const float*)d_in[2];
    const float* fw2 = (const float*)d_in[3];
    // d_in[4] = bw0 (unused by the dynamics)
    const float* bw1 = (const float*)d_in[5];
    const float* bw2 = (const float*)d_in[6];
    const float* y   = (const float*)d_in[7];
    float* out = (float*)d_out;

    cudaFuncSetAttribute(step_kernel, cudaFuncAttributeMaxDynamicSharedMemorySize, SMEM_BYTES);
    cudaFuncSetAttribute(c0_kernel,   cudaFuncAttributeMaxDynamicSharedMemorySize, SMEM_BYTES);

    __half *rx, *c0q, *s1base, *s2base, *fw0T, *fw1T, *bw1T;
    float *c0, *s3base;
    cudaGetSymbolAddress((void**)&rx, g_rx);
    cudaGetSymbolAddress((void**)&c0, g_c0);
    cudaGetSymbolAddress((void**)&c0q, g_c0q);
    cudaGetSymbolAddress((void**)&s1base, g_s1);
    cudaGetSymbolAddress((void**)&s2base, g_s2);
    cudaGetSymbolAddress((void**)&s3base, g_s3);
    cudaGetSymbolAddress((void**)&fw0T, g_fw0T);
    cudaGetSymbolAddress((void**)&fw1T, g_fw1T);
    cudaGetSymbolAddress((void**)&bw1T, g_bw1T);

    __half* s1p[2] = { s1base, s1base + (size_t)BSZ * HID };
    __half* s2p[2] = { s2base, s2base + (size_t)BSZ * HID };
    float*  s3p[2] = { s3base, s3base + (size_t)BSZ * NOUT };

    {
        dim3 blk(32, 8);
        transpose_kernel<<<dim3(HID / 32, NIN / 32), blk>>>(fw0, fw0T, NIN, HID);
        transpose_kernel<<<dim3(HID / 32, HID / 32), blk>>>(fw1, fw1T, HID, HID);
        transpose_kernel<<<dim3(HID / 32, HID / 32), blk>>>(bw1, bw1T, HID, HID);
    }

    clip_kernel<<<(BSZ * NIN + 255) / 256, 256>>>(x, rx, BSZ * NIN);

    // c0 = rx @ fw0 (loop-invariant), fp32 output
    c0_kernel<<<64, 256, SMEM_BYTES>>>(rx, fw0T, c0);

    // step 0 collapses to elementwise (states start at zero)
    init_kernel<<<(BSZ * HID + 255) / 256, 256>>>(c0, c0q, s1p[1], s2p[1], s3p[1]);

    for (int t = 1; t < STEPS_TOTAL; t++) {
        const int p = t & 1;
        const int q = 1 - p;
        const int weak = (t >= STEPS_FREE) ? 1 : 0;
        step_kernel<<<136, 256, SMEM_BYTES>>>(
            s1p[p], s2p[p], s3p[p],
            s1p[q], s2p[q], s3p[q],
            fw1T, bw1T, bw2, fw2, c0q, y, weak);
    }

    const int fin = STEPS_TOTAL & 1;
    concat_kernel<<<(BSZ * (2 * HID + NOUT) + 255) / 256, 256>>>(
        s1p[fin], s2p[fin], s3p[fin], out);
}

// round 10
// speedup vs baseline: 1.4574x; 1.1937x over previous
#include <cuda_runtime.h>
#include <cuda_fp16.h>
#include <cstdint>

#define BSZ 256
#define HID 4096
#define NIN 1024
#define NOUT 10
#define STEPS_TOTAL 25
#define STEPS_FREE 20
#define NCTA 136

// GEMM tiling: BM=BN=128, BK=64 halfs per iter, 256 threads (8 warps)
#define BKK 64
#define NSTAGE 4
#define ROWH 72                            // smem row stride in halfs (144 B)
#define STAGE_HALFS (2 * 128 * ROWH)       // A + B tiles
#define SMEM_BYTES (NSTAGE * STAGE_HALFS * 2)  // 147456 B

// ---------------- persistent device scratch ----------------
__device__ __align__(128) __half g_rx[BSZ * NIN];
__device__ __align__(128) float  g_c0[BSZ * HID];
__device__ __align__(128) __half g_c0q[BSZ * HID];      // 0.25*c0, fp16
__device__ __align__(128) __half g_s1[2][BSZ * HID];
__device__ __align__(128) __half g_s2[2][BSZ * HID];
__device__ __align__(128) float  g_s3[2][BSZ * NOUT];
__device__ __align__(128) __half g_fw0T[(size_t)HID * NIN];
__device__ __align__(128) __half g_fw1T[(size_t)HID * HID];
__device__ __align__(128) __half g_bw1T[(size_t)HID * HID];

// grid-barrier state (reset by init_kernel each launch)
__device__ unsigned g_cnt;
__device__ volatile unsigned g_gen;

// ---------------- helpers ----------------
__device__ __forceinline__ uint32_t smem_u32(const void* p) {
    uint32_t a;
    asm("{ .reg .u64 t; cvta.to.shared.u64 t, %1; cvt.u32.u64 %0, t; }"
        : "=r"(a) : "l"(p));
    return a;
}

__device__ __forceinline__ void cp16(uint32_t dst, const void* src) {
    asm volatile("cp.async.cg.shared.global [%0], [%1], 16;"
                 :: "r"(dst), "l"(src) : "memory");
}
#define CP_COMMIT() asm volatile("cp.async.commit_group;" ::: "memory")
#define CP_WAIT(n)  asm volatile("cp.async.wait_group %0;" :: "n"(n) : "memory")

__device__ __forceinline__ void ldsm4(uint32_t& r0, uint32_t& r1,
                                      uint32_t& r2, uint32_t& r3, uint32_t addr) {
    asm volatile("ldmatrix.sync.aligned.m8n8.x4.shared.b16 {%0,%1,%2,%3}, [%4];"
                 : "=r"(r0), "=r"(r1), "=r"(r2), "=r"(r3) : "r"(addr));
}

// m16n8k16 fp16 mma, fp32 accum
__device__ __forceinline__ void mma_f16(float* c, const uint32_t* a,
                                        uint32_t b0, uint32_t b1) {
    asm volatile(
        "mma.sync.aligned.m16n8k16.row.col.f32.f16.f16.f32 "
        "{%0,%1,%2,%3}, {%4,%5,%6,%7}, {%8,%9}, {%0,%1,%2,%3};"
        : "+f"(c[0]), "+f"(c[1]), "+f"(c[2]), "+f"(c[3])
        : "r"(a[0]), "r"(a[1]), "r"(a[2]), "r"(a[3]), "r"(b0), "r"(b1));
}

// grid-wide barrier; all NCTA CTAs must participate, all co-resident.
__device__ __forceinline__ void grid_bar(unsigned target) {
    __threadfence();          // each thread: make my writes visible
    __syncthreads();          // all threads of CTA fenced
    if (threadIdx.x == 0) {
        unsigned prev = atomicAdd(&g_cnt, 1u);
        if (prev == NCTA - 1) {
            g_cnt = 0u;
            __threadfence();
            g_gen = target;
        } else {
            while (g_gen < target) { }
        }
    }
    __syncthreads();
}

// ---------------- GEMM tile (device) — identical to R6 core ----------------
// [128,128] tile at (rowBase,colBase) of D[M,4096] = A[M,K] @ BT[4096,K]^T
// MODE 0: OutF = acc (fp32)                                   (c0)
// MODE 1: OutH = h(clip(0.5*Sold + C0q + 0.25*acc))           (s1; C0q = 0.25*c0)
// MODE 2: OutH = h(clip(0.5*Sold + 0.25*(acc + s3old@bw2)))   (s2)
template <int MODE>
__device__ __forceinline__ void gemm_tile(
    const __half* __restrict__ A, const __half* __restrict__ BT, int K,
    float* __restrict__ OutF, __half* __restrict__ OutH,
    const __half* __restrict__ Sold, const __half* __restrict__ C0q,
    const float* __restrict__ s3old, const float* __restrict__ bw2,
    int rowBase, int colBase, __half* smem)
{
    const int tid  = threadIdx.x;
    const int lane = tid & 31;
    const int wid  = tid >> 5;
    const int g = lane >> 2, q = lane & 3;
    const int warpM = wid & 3;   // 4 row-groups of 32
    const int warpN = wid >> 2;  // 2 col-groups of 64

    float acc[2][8][4];
#pragma unroll
    for (int mi = 0; mi < 2; mi++)
#pragma unroll
        for (int ni = 0; ni < 8; ni++)
#pragma unroll
            for (int t = 0; t < 4; t++) acc[mi][ni][t] = 0.0f;

    const int ldr  = tid >> 1;
    const int seg0 = (tid & 1) * 4;

    const __half* Ag = A  + (size_t)(rowBase + ldr) * K;
    const __half* Bg = BT + (size_t)(colBase + ldr) * K;

    const int nIt = K / BKK;

#define LOAD_STAGE(s, kt)                                            \
    do {                                                             \
        __half* As_ = smem + (s) * STAGE_HALFS;                      \
        __half* Bs_ = As_ + 128 * ROWH;                              \
        uint32_t dA = smem_u32(As_ + ldr * ROWH);                    \
        uint32_t dB = smem_u32(Bs_ + ldr * ROWH);                    \
        _Pragma("unroll")                                            \
        for (int u = 0; u < 4; u++) {                                \
            int sg = seg0 + u;                                       \
            cp16(dA + sg * 16, Ag + (kt) + sg * 8);                  \
            cp16(dB + sg * 16, Bg + (kt) + sg * 8);                  \
        }                                                            \
    } while (0)

    LOAD_STAGE(0, 0);       CP_COMMIT();
    LOAD_STAGE(1, BKK);     CP_COMMIT();
    LOAD_STAGE(2, 2 * BKK); CP_COMMIT();

    const int lrow = (lane & 7) + ((lane >> 3) & 1) * 8;
    const int lcolB = ((lane >> 4) & 1) * 16;   // bytes

    uint32_t a[2][2][4];   // [buf][mi][frag]
    uint32_t b[2][4][4];   // [buf][nj][frag]

#define LOAD_FRAGS(buf, aB, bB, ko)                                          \
    do {                                                                     \
        _Pragma("unroll")                                                    \
        for (int mi = 0; mi < 2; mi++)                                       \
            ldsm4(a[buf][mi][0], a[buf][mi][1], a[buf][mi][2], a[buf][mi][3],\
                  (aB) + mi * 16 * (ROWH * 2) + (ko));                       \
        _Pragma("unroll")                                                    \
        for (int nj = 0; nj < 4; nj++)                                       \
            ldsm4(b[buf][nj][0], b[buf][nj][1], b[buf][nj][2], b[buf][nj][3],\
                  (bB) + nj * 16 * (ROWH * 2) + (ko));                       \
    } while (0)

#define DO_MMA(buf)                                                          \
    do {                                                                     \
        _Pragma("unroll")                                                    \
        for (int nj = 0; nj < 4; nj++) {                                     \
            _Pragma("unroll")                                                \
            for (int mi = 0; mi < 2; mi++) {                                 \
                mma_f16(acc[mi][nj * 2 + 0], a[buf][mi],                     \
                        b[buf][nj][0], b[buf][nj][2]);                       \
                mma_f16(acc[mi][nj * 2 + 1], a[buf][mi],                     \
                        b[buf][nj][1], b[buf][nj][3]);                       \
            }                                                                \
        }                                                                    \
    } while (0)

    // prime: wait for stage 0, load its first k-step fragments
    CP_WAIT(2);
    __syncthreads();
    {
        const __half* As = smem;
        const __half* Bs = As + 128 * ROWH;
        const uint32_t aB = smem_u32(As + (warpM * 32 + lrow) * ROWH) + lcolB;
        const uint32_t bB = smem_u32(Bs + (warpN * 64 + lrow) * ROWH) + lcolB;
        LOAD_FRAGS(0, aB, bB, 0);
    }

    for (int it = 0; it < nIt; ++it) {
        if (it + 3 < nIt) {
            LOAD_STAGE((it + 3) & (NSTAGE - 1), (it + 3) * BKK);
        }
        CP_COMMIT();

        const __half* As = smem + (it & (NSTAGE - 1)) * STAGE_HALFS;
        const __half* Bs = As + 128 * ROWH;
        const uint32_t aB = smem_u32(As + (warpM * 32 + lrow) * ROWH) + lcolB;
        const uint32_t bB = smem_u32(Bs + (warpN * 64 + lrow) * ROWH) + lcolB;

        // k-steps 0..2: prefetch ks+1 into other buffer, then mma current
#pragma unroll
        for (int ks = 0; ks < 3; ks++) {
            LOAD_FRAGS((ks + 1) & 1, aB, bB, (ks + 1) * 32);
            DO_MMA(ks & 1);
        }

        // boundary: advance smem pipeline, prefetch next stage's k-step 0
        if (it + 1 < nIt) {
            CP_WAIT(2);
            __syncthreads();
            const __half* As2 = smem + ((it + 1) & (NSTAGE - 1)) * STAGE_HALFS;
            const __half* Bs2 = As2 + 128 * ROWH;
            const uint32_t aB2 = smem_u32(As2 + (warpM * 32 + lrow) * ROWH) + lcolB;
            const uint32_t bB2 = smem_u32(Bs2 + (warpN * 64 + lrow) * ROWH) + lcolB;
            LOAD_FRAGS(0, aB2, bB2, 0);
        }
        DO_MMA(1);   // k-step 3 lives in buffer 1
    }
#undef LOAD_FRAGS
#undef DO_MMA
#undef LOAD_STAGE

    // ---------------- epilogue ----------------
    const int rw = rowBase + warpM * 32;
    const int cw = colBase + warpN * 64;

    if (MODE == 2) {
        float s3r[2][2][10];
#pragma unroll
        for (int mi = 0; mi < 2; mi++)
#pragma unroll
            for (int h = 0; h < 2; h++) {
                const int r = rw + mi * 16 + h * 8 + g;
#pragma unroll
                for (int k = 0; k < NOUT; k++)
                    s3r[mi][h][k] = __ldcg(&s3old[r * NOUT + k]);  // cross-CTA: bypass L1
            }
#pragma unroll
        for (int ni = 0; ni < 8; ni++) {
            const int cb = cw + ni * 8 + q * 2;
#pragma unroll
            for (int k = 0; k < NOUT; k++) {
                const float2 b2 = *(const float2*)&bw2[(size_t)k * HID + cb];
#pragma unroll
                for (int mi = 0; mi < 2; mi++) {
                    acc[mi][ni][0] = fmaf(s3r[mi][0][k], b2.x, acc[mi][ni][0]);
                    acc[mi][ni][1] = fmaf(s3r[mi][0][k], b2.y, acc[mi][ni][1]);
                    acc[mi][ni][2] = fmaf(s3r[mi][1][k], b2.x, acc[mi][ni][2]);
                    acc[mi][ni][3] = fmaf(s3r[mi][1][k], b2.y, acc[mi][ni][3]);
                }
            }
        }
    }

#pragma unroll
    for (int mi = 0; mi < 2; mi++) {
#pragma unroll
        for (int ni = 0; ni < 8; ni++) {
            const int r0 = rw + mi * 16 + g;
            const int cb = cw + ni * 8 + q * 2;
#pragma unroll
            for (int h = 0; h < 2; h++) {
                const size_t idx = (size_t)(r0 + h * 8) * HID + cb;
                float vx = acc[mi][ni][h * 2 + 0];
                float vy = acc[mi][ni][h * 2 + 1];
                if (MODE == 0) {
                    *(float2*)&OutF[idx] = make_float2(vx, vy);
                } else {
                    // Sold tile written by THIS CTA (same bid) -> L1-safe
                    const float2 so = __half22float2(*(const __half2*)&Sold[idx]);
                    if (MODE == 1) {
                        const float2 c2 = __half22float2(*(const __half2*)&C0q[idx]);
                        vx = 0.5f * so.x + c2.x + 0.25f * vx;
                        vy = 0.5f * so.y + c2.y + 0.25f * vy;
                    } else {
                        vx = 0.5f * so.x + 0.25f * vx;
                        vy = 0.5f * so.y + 0.25f * vy;
                    }
                    vx = fminf(fmaxf(vx, 0.0f), 1.0f);
                    vy = fminf(fmaxf(vy, 0.0f), 1.0f);
                    *(__half2*)&OutH[idx] = __floats2half2_rn(vx, vy);
                }
            }
        }
    }
}

// ---------------- s3 tile (device): 32 rows, p3 = s2old @ fw2 ----------------
__device__ __forceinline__ void s3_tile(
    const __half* __restrict__ s2old, const float* __restrict__ fw2,
    const float* __restrict__ s3old, const float* __restrict__ y,
    float* __restrict__ s3new, int weak, int rowBase, __half* smem_raw)
{
    const int tid = threadIdx.x, lane = tid & 31, wid = tid >> 5;
    float* fs = (float*)smem_raw;
    float acc[4][NOUT];
#pragma unroll
    for (int r = 0; r < 4; r++)
#pragma unroll
        for (int j = 0; j < NOUT; j++) acc[r][j] = 0.0f;

    for (int c = 0; c < 8; c++) {
        __syncthreads();
        for (int i = tid; i < 512 * NOUT; i += 256) {
            int kl = i / NOUT, j = i - kl * NOUT;
            fs[kl * 11 + j] = fw2[(size_t)(c * 512 + kl) * NOUT + j];
        }
        __syncthreads();
#pragma unroll
        for (int r = 0; r < 4; r++) {
            const int row = rowBase + wid * 4 + r;
            const __half* s2r = s2old + (size_t)row * HID + c * 512;
#pragma unroll 4
            for (int i = 0; i < 16; i++) {
                const int kl = lane + i * 32;
                const float sv = __half2float(__ldcg(&s2r[kl]));   // cross-CTA: bypass L1
#pragma unroll
                for (int j = 0; j < NOUT; j++)
                    acc[r][j] = fmaf(sv, fs[kl * 11 + j], acc[r][j]);
            }
        }
    }

#pragma unroll
    for (int r = 0; r < 4; r++) {
        const int row = rowBase + wid * 4 + r;
#pragma unroll
        for (int j = 0; j < NOUT; j++) {
            float v = acc[r][j];
#pragma unroll
            for (int o = 16; o; o >>= 1) v += __shfl_xor_sync(0xffffffffu, v, o);
            if (lane == 0) {
                float out = weak ? 0.5f * (v + y[row * NOUT + j])
                                 : 0.5f * (__ldcg(&s3old[row * NOUT + j]) + v);
                s3new[row * NOUT + j] = fminf(fmaxf(out, 0.0f), 1.0f);
            }
        }
    }
}

// ---------------- persistent step kernel: 136 CTAs, 24 steps, grid barrier ----
__global__ __launch_bounds__(256, 1) void step_persist(
    __half* __restrict__ s1a, __half* __restrict__ s1b,
    __half* __restrict__ s2a, __half* __restrict__ s2b,
    float* __restrict__ s3a, float* __restrict__ s3b,
    const __half* __restrict__ fw1T, const __half* __restrict__ bw1T,
    const float* __restrict__ bw2, const float* __restrict__ fw2,
    const __half* __restrict__ c0q, const float* __restrict__ y)
{
    extern __shared__ __half smem[];
    const int bid = blockIdx.x;

    for (int t = 1; t < STEPS_TOTAL; t++) {
        if (t > 1) grid_bar((unsigned)(t - 1));   // all CTAs finished step t-1

        const int p = t & 1;
        const __half* s1old = p ? s1b : s1a;
        const __half* s2old = p ? s2b : s2a;
        const float*  s3old = p ? s3b : s3a;
        __half* s1new = p ? s1a : s1b;
        __half* s2new = p ? s2a : s2b;
        float*  s3new = p ? s3a : s3b;
        const int weak = (t >= STEPS_FREE) ? 1 : 0;

        if (bid < 64) {
            gemm_tile<1>(s2old, bw1T, HID, nullptr, s1new, s1old, c0q, nullptr, nullptr,
                         (bid >> 5) * 128, (bid & 31) * 128, smem);
        } else if (bid < 128) {
            const int tt = bid - 64;
            gemm_tile<2>(s1old, fw1T, HID, nullptr, s2new, s2old, nullptr, s3old, bw2,
                         (tt >> 5) * 128, (tt & 31) * 128, smem);
        } else {
            s3_tile(s2old, fw2, s3old, y, s3new, weak, (bid - 128) * 32, smem);
        }
    }
}

__global__ __launch_bounds__(256, 1) void c0_kernel(
    const __half* __restrict__ rx, const __half* __restrict__ fw0T,
    float* __restrict__ c0)
{
    extern __shared__ __half smem[];
    const int bid = blockIdx.x;
    gemm_tile<0>(rx, fw0T, NIN, c0, nullptr, nullptr, nullptr, nullptr, nullptr,
                 (bid >> 5) * 128, (bid & 31) * 128, smem);
}

// ---------------- small kernels ----------------
__global__ void clip_kernel(const float* __restrict__ x, __half* __restrict__ rx, int n) {
    int i = blockIdx.x * blockDim.x + threadIdx.x;
    if (i < n) rx[i] = __float2half_rn(fminf(fmaxf(x[i], 0.0f), 1.0f));
}

// step 0 from zero states + barrier-state reset (graph-replay determinism)
__global__ void init_kernel(const float* __restrict__ c0, __half* __restrict__ c0q,
                            __half* __restrict__ s1, __half* __restrict__ s2,
                            float* __restrict__ s3) {
    int i = blockIdx.x * blockDim.x + threadIdx.x;
    if (i == 0) { g_cnt = 0u; g_gen = 0u; }
    if (i < BSZ * HID) {
        float qc = 0.25f * c0[i];
        c0q[i] = __float2half_rn(qc);
        s1[i] = __float2half_rn(fminf(fmaxf(qc, 0.0f), 1.0f));
        s2[i] = __half(0.0f);
    }
    if (i < BSZ * NOUT) s3[i] = 0.0f;
}

// dst[c][r] = h(src[r][c]); src fp32 [R,C], dst fp16 [C,R]
__global__ void transpose_kernel(const float* __restrict__ src, __half* __restrict__ dst,
                                 int R, int C) {
    __shared__ float tile[32][33];
    int bx = blockIdx.x * 32, by = blockIdx.y * 32;
    int x = bx + threadIdx.x;
    int y = by + threadIdx.y;
#pragma unroll
    for (int i = 0; i < 32; i += 8)
        tile[threadIdx.y + i][threadIdx.x] = src[(size_t)(y + i) * C + x];
    __syncthreads();
    x = by + threadIdx.x;
    y = bx + threadIdx.y;
#pragma unroll
    for (int i = 0; i < 32; i += 8)
        dst[(size_t)(y + i) * R + x] = __float2half_rn(tile[threadIdx.x][threadIdx.y + i]);
}

__global__ void concat_kernel(const __half* __restrict__ s1,
                              const __half* __restrict__ s2,
                              const float* __restrict__ s3,
                              float* __restrict__ out)
{
    int i = blockIdx.x * blockDim.x + threadIdx.x;
    const int W = HID + HID + NOUT;
    if (i >= BSZ * W) return;
    int row = i / W;
    int c = i - row * W;
    float v;
    if (c < HID)          v = __half2float(s1[(size_t)row * HID + c]);
    else if (c < 2 * HID) v = __half2float(s2[(size_t)row * HID + (c - HID)]);
    else                  v = s3[row * NOUT + (c - 2 * HID)];
    out[i] = v;
}

// ---------------- launch ----------------
extern "C" void kernel_launch(void* const* d_in, const int* in_sizes, int n_in,
                              void* d_out, int out_size)
{
    const float* x   = (const float*)d_in[0];
    const float* fw0 = (const float*)d_in[1];
    const float* fw1 = (const float*)d_in[2];
    const float* fw2 = (const float*)d_in[3];
    // d_in[4] = bw0 (unused by the dynamics)
    const float* bw1 = (const float*)d_in[5];
    const float* bw2 = (const float*)d_in[6];
    const float* y   = (const float*)d_in[7];
    float* out = (float*)d_out;

    cudaFuncSetAttribute(step_persist, cudaFuncAttributeMaxDynamicSharedMemorySize, SMEM_BYTES);
    cudaFuncSetAttribute(c0_kernel,    cudaFuncAttributeMaxDynamicSharedMemorySize, SMEM_BYTES);

    __half *rx, *c0q, *s1base, *s2base, *fw0T, *fw1T, *bw1T;
    float *c0, *s3base;
    cudaGetSymbolAddress((void**)&rx, g_rx);
    cudaGetSymbolAddress((void**)&c0, g_c0);
    cudaGetSymbolAddress((void**)&c0q, g_c0q);
    cudaGetSymbolAddress((void**)&s1base, g_s1);
    cudaGetSymbolAddress((void**)&s2base, g_s2);
    cudaGetSymbolAddress((void**)&s3base, g_s3);
    cudaGetSymbolAddress((void**)&fw0T, g_fw0T);
    cudaGetSymbolAddress((void**)&fw1T, g_fw1T);
    cudaGetSymbolAddress((void**)&bw1T, g_bw1T);

    __half* s1p[2] = { s1base, s1base + (size_t)BSZ * HID };
    __half* s2p[2] = { s2base, s2base + (size_t)BSZ * HID };
    float*  s3p[2] = { s3base, s3base + (size_t)BSZ * NOUT };

    {
        dim3 blk(32, 8);
        transpose_kernel<<<dim3(HID / 32, NIN / 32), blk>>>(fw0, fw0T, NIN, HID);
        transpose_kernel<<<dim3(HID / 32, HID / 32), blk>>>(fw1, fw1T, HID, HID);
        transpose_kernel<<<dim3(HID / 32, HID / 32), blk>>>(bw1, bw1T, HID, HID);
    }

    clip_kernel<<<(BSZ * NIN + 255) / 256, 256>>>(x, rx, BSZ * NIN);

    // c0 = rx @ fw0 (loop-invariant), fp32 output
    c0_kernel<<<64, 256, SMEM_BYTES>>>(rx, fw0T, c0);

    // step 0 collapses to elementwise (states start at zero); resets barrier state
    init_kernel<<<(BSZ * HID + 255) / 256, 256>>>(c0, c0q, s1p[1], s2p[1], s3p[1]);

    // steps 1..24 in ONE persistent launch (136 CTAs, all co-resident)
    step_persist<<<NCTA, 256, SMEM_BYTES>>>(
        s1p[0], s1p[1], s2p[0], s2p[1], s3p[0], s3p[1],
        fw1T, bw1T, bw2, fw2, c0q, y);

    const int fin = STEPS_TOTAL & 1;
    concat_kernel<<<(BSZ * (2 * HID + NOUT) + 255) / 256, 256>>>(
        s1p[fin], s2p[fin], s3p[fin], out);
}

// round 11
// speedup vs baseline: 1.4800x; 1.0155x over previous
#include <cuda_runtime.h>
#include <cuda_fp16.h>
#include <cstdint>

#define BSZ 256
#define HID 4096
#define NIN 1024
#define NOUT 10
#define STEPS_TOTAL 25
#define STEPS_FREE 20
#define OUTW (2 * HID + NOUT)   // 8202

// GEMM tiling: BM=BN=128, BK=64 halfs per iter, 256 threads (8 warps)
#define BKK 64
#define NSTAGE 4
#define ROWH 72                            // smem row stride in halfs (144 B)
#define STAGE_HALFS (2 * 128 * ROWH)       // A + B tiles
#define SMEM_BYTES (NSTAGE * STAGE_HALFS * 2)  // 147456 B

// ---------------- persistent device scratch ----------------
__device__ __align__(128) __half g_rx[BSZ * NIN];
__device__ __align__(128) float  g_c0[BSZ * HID];
__device__ __align__(128) __half g_c0q[BSZ * HID];      // 0.25*c0, fp16
__device__ __align__(128) __half g_s1[2][BSZ * HID];
__device__ __align__(128) __half g_s2[2][BSZ * HID];
__device__ __align__(128) float  g_s3[2][BSZ * NOUT];
__device__ __align__(128) __half g_fw0T[(size_t)HID * NIN];
__device__ __align__(128) __half g_fw1T[(size_t)HID * HID];
__device__ __align__(128) __half g_bw1T[(size_t)HID * HID];

// ---------------- helpers ----------------
__device__ __forceinline__ uint32_t smem_u32(const void* p) {
    uint32_t a;
    asm("{ .reg .u64 t; cvta.to.shared.u64 t, %1; cvt.u32.u64 %0, t; }"
        : "=r"(a) : "l"(p));
    return a;
}

__device__ __forceinline__ void cp16(uint32_t dst, const void* src) {
    asm volatile("cp.async.cg.shared.global [%0], [%1], 16;"
                 :: "r"(dst), "l"(src) : "memory");
}
#define CP_COMMIT() asm volatile("cp.async.commit_group;" ::: "memory")
#define CP_WAIT(n)  asm volatile("cp.async.wait_group %0;" :: "n"(n) : "memory")

__device__ __forceinline__ void ldsm4(uint32_t& r0, uint32_t& r1,
                                      uint32_t& r2, uint32_t& r3, uint32_t addr) {
    asm volatile("ldmatrix.sync.aligned.m8n8.x4.shared.b16 {%0,%1,%2,%3}, [%4];"
                 : "=r"(r0), "=r"(r1), "=r"(r2), "=r"(r3) : "r"(addr));
}

// m16n8k16 fp16 mma, fp32 accum
__device__ __forceinline__ void mma_f16(float* c, const uint32_t* a,
                                        uint32_t b0, uint32_t b1) {
    asm volatile(
        "mma.sync.aligned.m16n8k16.row.col.f32.f16.f16.f32 "
        "{%0,%1,%2,%3}, {%4,%5,%6,%7}, {%8,%9}, {%0,%1,%2,%3};"
        : "+f"(c[0]), "+f"(c[1]), "+f"(c[2]), "+f"(c[3])
        : "r"(a[0]), "r"(a[1]), "r"(a[2]), "r"(a[3]), "r"(b0), "r"(b1));
}

// ---------------- GEMM tile (device) — R6 core ----------------
// [128,128] tile at (rowBase,colBase) of D[M,4096] = A[M,K] @ BT[4096,K]^T
// MODE 0: OutF = acc (fp32)                                   (c0)
// MODE 1: v = clip(0.5*Sold + C0q + 0.25*acc)                 (s1; C0q = 0.25*c0)
// MODE 2: v = clip(0.5*Sold + 0.25*(acc + s3old@bw2))         (s2)
// FINAL=false: OutH = h(v);  FINAL=true: fOut[row*OUTW + fColOff + col] = v (fp32)
template <int MODE, bool FINAL>
__device__ __forceinline__ void gemm_tile(
    const __half* __restrict__ A, const __half* __restrict__ BT, int K,
    float* __restrict__ OutF, __half* __restrict__ OutH,
    const __half* __restrict__ Sold, const __half* __restrict__ C0q,
    const float* __restrict__ s3old, const float* __restrict__ bw2,
    float* __restrict__ fOut, int fColOff,
    int rowBase, int colBase, __half* smem)
{
    const int tid  = threadIdx.x;
    const int lane = tid & 31;
    const int wid  = tid >> 5;
    const int g = lane >> 2, q = lane & 3;
    const int warpM = wid & 3;   // 4 row-groups of 32
    const int warpN = wid >> 2;  // 2 col-groups of 64

    float acc[2][8][4];
#pragma unroll
    for (int mi = 0; mi < 2; mi++)
#pragma unroll
        for (int ni = 0; ni < 8; ni++)
#pragma unroll
            for (int t = 0; t < 4; t++) acc[mi][ni][t] = 0.0f;

    const int ldr  = tid >> 1;
    const int seg0 = (tid & 1) * 4;

    const __half* Ag = A  + (size_t)(rowBase + ldr) * K;
    const __half* Bg = BT + (size_t)(colBase + ldr) * K;

    const int nIt = K / BKK;

#define LOAD_STAGE(s, kt)                                            \
    do {                                                             \
        __half* As_ = smem + (s) * STAGE_HALFS;                      \
        __half* Bs_ = As_ + 128 * ROWH;                              \
        uint32_t dA = smem_u32(As_ + ldr * ROWH);                    \
        uint32_t dB = smem_u32(Bs_ + ldr * ROWH);                    \
        _Pragma("unroll")                                            \
        for (int u = 0; u < 4; u++) {                                \
            int sg = seg0 + u;                                       \
            cp16(dA + sg * 16, Ag + (kt) + sg * 8);                  \
            cp16(dB + sg * 16, Bg + (kt) + sg * 8);                  \
        }                                                            \
    } while (0)

    LOAD_STAGE(0, 0);       CP_COMMIT();
    LOAD_STAGE(1, BKK);     CP_COMMIT();
    LOAD_STAGE(2, 2 * BKK); CP_COMMIT();

    const int lrow = (lane & 7) + ((lane >> 3) & 1) * 8;
    const int lcolB = ((lane >> 4) & 1) * 16;   // bytes

    uint32_t a[2][2][4];   // [buf][mi][frag]
    uint32_t b[2][4][4];   // [buf][nj][frag]

#define LOAD_FRAGS(buf, aB, bB, ko)                                          \
    do {                                                                     \
        _Pragma("unroll")                                                    \
        for (int mi = 0; mi < 2; mi++)                                       \
            ldsm4(a[buf][mi][0], a[buf][mi][1], a[buf][mi][2], a[buf][mi][3],\
                  (aB) + mi * 16 * (ROWH * 2) + (ko));                       \
        _Pragma("unroll")                                                    \
        for (int nj = 0; nj < 4; nj++)                                       \
            ldsm4(b[buf][nj][0], b[buf][nj][1], b[buf][nj][2], b[buf][nj][3],\
                  (bB) + nj * 16 * (ROWH * 2) + (ko));                       \
    } while (0)

#define DO_MMA(buf)                                                          \
    do {                                                                     \
        _Pragma("unroll")                                                    \
        for (int nj = 0; nj < 4; nj++) {                                     \
            _Pragma("unroll")                                                \
            for (int mi = 0; mi < 2; mi++) {                                 \
                mma_f16(acc[mi][nj * 2 + 0], a[buf][mi],                     \
                        b[buf][nj][0], b[buf][nj][2]);                       \
                mma_f16(acc[mi][nj * 2 + 1], a[buf][mi],                     \
                        b[buf][nj][1], b[buf][nj][3]);                       \
            }                                                                \
        }                                                                    \
    } while (0)

    // prime: wait for stage 0, load its first k-step fragments
    CP_WAIT(2);
    __syncthreads();
    {
        const __half* As = smem;
        const __half* Bs = As + 128 * ROWH;
        const uint32_t aB = smem_u32(As + (warpM * 32 + lrow) * ROWH) + lcolB;
        const uint32_t bB = smem_u32(Bs + (warpN * 64 + lrow) * ROWH) + lcolB;
        LOAD_FRAGS(0, aB, bB, 0);
    }

    for (int it = 0; it < nIt; ++it) {
        if (it + 3 < nIt) {
            LOAD_STAGE((it + 3) & (NSTAGE - 1), (it + 3) * BKK);
        }
        CP_COMMIT();

        const __half* As = smem + (it & (NSTAGE - 1)) * STAGE_HALFS;
        const __half* Bs = As + 128 * ROWH;
        const uint32_t aB = smem_u32(As + (warpM * 32 + lrow) * ROWH) + lcolB;
        const uint32_t bB = smem_u32(Bs + (warpN * 64 + lrow) * ROWH) + lcolB;

        // k-steps 0..2: prefetch ks+1 into other buffer, then mma current
#pragma unroll
        for (int ks = 0; ks < 3; ks++) {
            LOAD_FRAGS((ks + 1) & 1, aB, bB, (ks + 1) * 32);
            DO_MMA(ks & 1);
        }

        // boundary: advance smem pipeline, prefetch next stage's k-step 0
        if (it + 1 < nIt) {
            CP_WAIT(2);
            __syncthreads();
            const __half* As2 = smem + ((it + 1) & (NSTAGE - 1)) * STAGE_HALFS;
            const __half* Bs2 = As2 + 128 * ROWH;
            const uint32_t aB2 = smem_u32(As2 + (warpM * 32 + lrow) * ROWH) + lcolB;
            const uint32_t bB2 = smem_u32(Bs2 + (warpN * 64 + lrow) * ROWH) + lcolB;
            LOAD_FRAGS(0, aB2, bB2, 0);
        }
        DO_MMA(1);   // k-step 3 lives in buffer 1
    }
#undef LOAD_FRAGS
#undef DO_MMA
#undef LOAD_STAGE

    // ---------------- epilogue ----------------
    const int rw = rowBase + warpM * 32;
    const int cw = colBase + warpN * 64;

    if (MODE == 2) {
        float s3r[2][2][10];
#pragma unroll
        for (int mi = 0; mi < 2; mi++)
#pragma unroll
            for (int h = 0; h < 2; h++) {
                const int r = rw + mi * 16 + h * 8 + g;
#pragma unroll
                for (int k = 0; k < NOUT; k++)
                    s3r[mi][h][k] = s3old[r * NOUT + k];
            }
#pragma unroll
        for (int ni = 0; ni < 8; ni++) {
            const int cb = cw + ni * 8 + q * 2;
#pragma unroll
            for (int k = 0; k < NOUT; k++) {
                const float2 b2 = *(const float2*)&bw2[(size_t)k * HID + cb];
#pragma unroll
                for (int mi = 0; mi < 2; mi++) {
                    acc[mi][ni][0] = fmaf(s3r[mi][0][k], b2.x, acc[mi][ni][0]);
                    acc[mi][ni][1] = fmaf(s3r[mi][0][k], b2.y, acc[mi][ni][1]);
                    acc[mi][ni][2] = fmaf(s3r[mi][1][k], b2.x, acc[mi][ni][2]);
                    acc[mi][ni][3] = fmaf(s3r[mi][1][k], b2.y, acc[mi][ni][3]);
                }
            }
        }
    }

#pragma unroll
    for (int mi = 0; mi < 2; mi++) {
#pragma unroll
        for (int ni = 0; ni < 8; ni++) {
            const int r0 = rw + mi * 16 + g;
            const int cb = cw + ni * 8 + q * 2;
#pragma unroll
            for (int h = 0; h < 2; h++) {
                const int row = r0 + h * 8;
                const size_t idx = (size_t)row * HID + cb;
                float vx = acc[mi][ni][h * 2 + 0];
                float vy = acc[mi][ni][h * 2 + 1];
                if (MODE == 0) {
                    *(float2*)&OutF[idx] = make_float2(vx, vy);
                } else {
                    const float2 so = __half22float2(*(const __half2*)&Sold[idx]);
                    if (MODE == 1) {
                        const float2 c2 = __half22float2(*(const __half2*)&C0q[idx]);
                        vx = 0.5f * so.x + c2.x + 0.25f * vx;
                        vy = 0.5f * so.y + c2.y + 0.25f * vy;
                    } else {
                        vx = 0.5f * so.x + 0.25f * vx;
                        vy = 0.5f * so.y + 0.25f * vy;
                    }
                    vx = fminf(fmaxf(vx, 0.0f), 1.0f);
                    vy = fminf(fmaxf(vy, 0.0f), 1.0f);
                    if (FINAL) {
                        // write final fp32 states straight into d_out
                        *(float2*)&fOut[(size_t)row * OUTW + fColOff + cb] =
                            make_float2(vx, vy);
                    } else {
                        *(__half2*)&OutH[idx] = __floats2half2_rn(vx, vy);
                    }
                }
            }
        }
    }
}

// ---------------- s3 tile (device): 32 rows, p3 = s2old @ fw2 ----------------
template <bool FINAL>
__device__ __forceinline__ void s3_tile(
    const __half* __restrict__ s2old, const float* __restrict__ fw2,
    const float* __restrict__ s3old, const float* __restrict__ y,
    float* __restrict__ s3new, float* __restrict__ fOut,
    int weak, int rowBase, __half* smem_raw)
{
    const int tid = threadIdx.x, lane = tid & 31, wid = tid >> 5;
    float* fs = (float*)smem_raw;
    float acc[4][NOUT];
#pragma unroll
    for (int r = 0; r < 4; r++)
#pragma unroll
        for (int j = 0; j < NOUT; j++) acc[r][j] = 0.0f;

    for (int c = 0; c < 8; c++) {
        __syncthreads();
        for (int i = tid; i < 512 * NOUT; i += 256) {
            int kl = i / NOUT, j = i - kl * NOUT;
            fs[kl * 11 + j] = fw2[(size_t)(c * 512 + kl) * NOUT + j];
        }
        __syncthreads();
#pragma unroll
        for (int r = 0; r < 4; r++) {
            const int row = rowBase + wid * 4 + r;
            const __half* s2r = s2old + (size_t)row * HID + c * 512;
#pragma unroll 4
            for (int i = 0; i < 16; i++) {
                const int kl = lane + i * 32;
                const float sv = __half2float(s2r[kl]);
#pragma unroll
                for (int j = 0; j < NOUT; j++)
                    acc[r][j] = fmaf(sv, fs[kl * 11 + j], acc[r][j]);
            }
        }
    }

#pragma unroll
    for (int r = 0; r < 4; r++) {
        const int row = rowBase + wid * 4 + r;
#pragma unroll
        for (int j = 0; j < NOUT; j++) {
            float v = acc[r][j];
#pragma unroll
            for (int o = 16; o; o >>= 1) v += __shfl_xor_sync(0xffffffffu, v, o);
            if (lane == 0) {
                float out = weak ? 0.5f * (v + y[row * NOUT + j])
                                 : 0.5f * (s3old[row * NOUT + j] + v);
                out = fminf(fmaxf(out, 0.0f), 1.0f);
                if (FINAL) fOut[(size_t)row * OUTW + 2 * HID + j] = out;
                else       s3new[row * NOUT + j] = out;
            }
        }
    }
}

// ---------------- fused step kernel: 136 CTAs = one wave ----------------
template <bool FINAL>
__global__ __launch_bounds__(256, 1) void step_kernel(
    const __half* __restrict__ s1old, const __half* __restrict__ s2old,
    const float* __restrict__ s3old,
    __half* __restrict__ s1new, __half* __restrict__ s2new, float* __restrict__ s3new,
    const __half* __restrict__ fw1T, const __half* __restrict__ bw1T,
    const float* __restrict__ bw2, const float* __restrict__ fw2,
    const __half* __restrict__ c0q, const float* __restrict__ y,
    float* __restrict__ fOut, int weak)
{
    extern __shared__ __half smem[];
    const int bid = blockIdx.x;
    if (bid < 64) {
        gemm_tile<1, FINAL>(s2old, bw1T, HID, nullptr, s1new, s1old, c0q, nullptr,
                            nullptr, fOut, 0,
                            (bid >> 5) * 128, (bid & 31) * 128, smem);
    } else if (bid < 128) {
        const int t = bid - 64;
        gemm_tile<2, FINAL>(s1old, fw1T, HID, nullptr, s2new, s2old, nullptr, s3old,
                            bw2, fOut, HID,
                            (t >> 5) * 128, (t & 31) * 128, smem);
    } else {
        s3_tile<FINAL>(s2old, fw2, s3old, y, s3new, fOut, weak, (bid - 128) * 32, smem);
    }
}

__global__ __launch_bounds__(256, 1) void c0_kernel(
    const __half* __restrict__ rx, const __half* __restrict__ fw0T,
    float* __restrict__ c0)
{
    extern __shared__ __half smem[];
    const int bid = blockIdx.x;
    gemm_tile<0, false>(rx, fw0T, NIN, c0, nullptr, nullptr, nullptr, nullptr,
                        nullptr, nullptr, 0,
                        (bid >> 5) * 128, (bid & 31) * 128, smem);
}

// ---------------- small kernels ----------------
__global__ void clip_kernel(const float* __restrict__ x, __half* __restrict__ rx, int n) {
    int i = blockIdx.x * blockDim.x + threadIdx.x;
    if (i < n) rx[i] = __float2half_rn(fminf(fmaxf(x[i], 0.0f), 1.0f));
}

__global__ void init_kernel(const float* __restrict__ c0, __half* __restrict__ c0q,
                            __half* __restrict__ s1, __half* __restrict__ s2,
                            float* __restrict__ s3) {
    int i = blockIdx.x * blockDim.x + threadIdx.x;
    if (i < BSZ * HID) {
        float qc = 0.25f * c0[i];
        c0q[i] = __float2half_rn(qc);
        s1[i] = __float2half_rn(fminf(fmaxf(qc, 0.0f), 1.0f));
        s2[i] = __half(0.0f);
    }
    if (i < BSZ * NOUT) s3[i] = 0.0f;
}

// 64x64-tile transpose+convert: dst[c][r] = h(src[r][c]); full-width fp16 stores.
// src fp32 [R,C]; grid (C/64, R/64); block (32,8).
__global__ void transpose64_kernel(const float* __restrict__ src,
                                   __half* __restrict__ dst, int R, int C) {
    __shared__ float tile[64][65];
    const int bx = blockIdx.x * 64;   // src col tile
    const int by = blockIdx.y * 64;   // src row tile
    const int tx = threadIdx.x, ty = threadIdx.y;
#pragma unroll
    for (int j = 0; j < 2; j++)
#pragma unroll
        for (int i = 0; i < 8; i++)
            tile[ty + i * 8][tx + j * 32] =
                src[(size_t)(by + ty + i * 8) * C + bx + tx + j * 32];
    __syncthreads();
#pragma unroll
    for (int i = 0; i < 8; i++) {
        const int cc = bx + ty + i * 8;          // dst row = src col
        const int k = ty + i * 8;
        __half2 v = __floats2half2_rn(tile[tx * 2][k], tile[tx * 2 + 1][k]);
        *(__half2*)&dst[(size_t)cc * R + by + tx * 2] = v;   // dst cols = src rows
    }
}

// ---------------- launch ----------------
extern "C" void kernel_launch(void* const* d_in, const int* in_sizes, int n_in,
                              void* d_out, int out_size)
{
    const float* x   = (const float*)d_in[0];
    const float* fw0 = (const float*)d_in[1];
    const float* fw1 = (const float*)d_in[2];
    const float* fw2 = (const float*)d_in[3];
    // d_in[4] = bw0 (unused by the dynamics)
    const float* bw1 = (const float*)d_in[5];
    const float* bw2 = (const float*)d_in[6];
    const float* y   = (const float*)d_in[7];
    float* out = (float*)d_out;

    cudaFuncSetAttribute(step_kernel<false>, cudaFuncAttributeMaxDynamicSharedMemorySize, SMEM_BYTES);
    cudaFuncSetAttribute(step_kernel<true>,  cudaFuncAttributeMaxDynamicSharedMemorySize, SMEM_BYTES);
    cudaFuncSetAttribute(c0_kernel,          cudaFuncAttributeMaxDynamicSharedMemorySize, SMEM_BYTES);

    __half *rx, *c0q, *s1base, *s2base, *fw0T, *fw1T, *bw1T;
    float *c0, *s3base;
    cudaGetSymbolAddress((void**)&rx, g_rx);
    cudaGetSymbolAddress((void**)&c0, g_c0);
    cudaGetSymbolAddress((void**)&c0q, g_c0q);
    cudaGetSymbolAddress((void**)&s1base, g_s1);
    cudaGetSymbolAddress((void**)&s2base, g_s2);
    cudaGetSymbolAddress((void**)&s3base, g_s3);
    cudaGetSymbolAddress((void**)&fw0T, g_fw0T);
    cudaGetSymbolAddress((void**)&fw1T, g_fw1T);
    cudaGetSymbolAddress((void**)&bw1T, g_bw1T);

    __half* s1p[2] = { s1base, s1base + (size_t)BSZ * HID };
    __half* s2p[2] = { s2base, s2base + (size_t)BSZ * HID };
    float*  s3p[2] = { s3base, s3base + (size_t)BSZ * NOUT };

    {
        dim3 blk(32, 8);
        transpose64_kernel<<<dim3(HID / 64, NIN / 64), blk>>>(fw0, fw0T, NIN, HID);
        transpose64_kernel<<<dim3(HID / 64, HID / 64), blk>>>(fw1, fw1T, HID, HID);
        transpose64_kernel<<<dim3(HID / 64, HID / 64), blk>>>(bw1, bw1T, HID, HID);
    }

    clip_kernel<<<(BSZ * NIN + 255) / 256, 256>>>(x, rx, BSZ * NIN);

    // c0 = rx @ fw0 (loop-invariant), fp32 output
    c0_kernel<<<64, 256, SMEM_BYTES>>>(rx, fw0T, c0);

    // step 0 collapses to elementwise (states start at zero)
    init_kernel<<<(BSZ * HID + 255) / 256, 256>>>(c0, c0q, s1p[1], s2p[1], s3p[1]);

    // steps 1..23 write fp16 state buffers
    for (int t = 1; t < STEPS_TOTAL - 1; t++) {
        const int p = t & 1;
        const int q = 1 - p;
        const int weak = (t >= STEPS_FREE) ? 1 : 0;
        step_kernel<false><<<136, 256, SMEM_BYTES>>>(
            s1p[p], s2p[p], s3p[p],
            s1p[q], s2p[q], s3p[q],
            fw1T, bw1T, bw2, fw2, c0q, y, nullptr, weak);
    }

    // final step (t = 24) writes fp32 results directly into d_out
    {
        const int t = STEPS_TOTAL - 1;   // 24
        const int p = t & 1;             // 0
        const int q = 1 - p;
        step_kernel<true><<<136, 256, SMEM_BYTES>>>(
            s1p[p], s2p[p], s3p[p],
            s1p[q], s2p[q], s3p[q],
            fw1T, bw1T, bw2, fw2, c0q, y, out, 1);
    }
}

// round 12
// speedup vs baseline: 2.2352x; 1.5103x over previous
#include <cuda_runtime.h>
#include <cuda_fp16.h>
#include <cstdint>

#define BSZ 256
#define HID 4096
#define NIN 1024
#define NOUT 10
#define STEPS_TOTAL 25
#define STEPS_FREE 20
#define OUTW (2 * HID + NOUT)   // 8202
#define NTHREADS 512

// GEMM tiling: BM=BN=128, BK=64 halfs per iter, 512 threads (16 warps, warp tile 32x32)
#define BKK 64
#define NSTAGE 4
#define ROWH 72                            // smem row stride in halfs (144 B)
#define STAGE_HALFS (2 * 128 * ROWH)       // A + B tiles
#define SMEM_BYTES (NSTAGE * STAGE_HALFS * 2)  // 147456 B

// ---------------- persistent device scratch ----------------
__device__ __align__(128) __half g_rx[BSZ * NIN];
__device__ __align__(128) float  g_c0[BSZ * HID];
__device__ __align__(128) __half g_c0q[BSZ * HID];      // 0.25*c0, fp16
__device__ __align__(128) __half g_s1[2][BSZ * HID];
__device__ __align__(128) __half g_s2[2][BSZ * HID];
__device__ __align__(128) float  g_s3[2][BSZ * NOUT];
__device__ __align__(128) __half g_fw0T[(size_t)HID * NIN];
__device__ __align__(128) __half g_fw1T[(size_t)HID * HID];
__device__ __align__(128) __half g_bw1T[(size_t)HID * HID];

// ---------------- helpers ----------------
__device__ __forceinline__ uint32_t smem_u32(const void* p) {
    uint32_t a;
    asm("{ .reg .u64 t; cvta.to.shared.u64 t, %1; cvt.u32.u64 %0, t; }"
        : "=r"(a) : "l"(p));
    return a;
}

__device__ __forceinline__ void cp16(uint32_t dst, const void* src) {
    asm volatile("cp.async.cg.shared.global [%0], [%1], 16;"
                 :: "r"(dst), "l"(src) : "memory");
}
#define CP_COMMIT() asm volatile("cp.async.commit_group;" ::: "memory")
#define CP_WAIT(n)  asm volatile("cp.async.wait_group %0;" :: "n"(n) : "memory")

__device__ __forceinline__ void ldsm4(uint32_t& r0, uint32_t& r1,
                                      uint32_t& r2, uint32_t& r3, uint32_t addr) {
    asm volatile("ldmatrix.sync.aligned.m8n8.x4.shared.b16 {%0,%1,%2,%3}, [%4];"
                 : "=r"(r0), "=r"(r1), "=r"(r2), "=r"(r3) : "r"(addr));
}

// m16n8k16 fp16 mma, fp32 accum
__device__ __forceinline__ void mma_f16(float* c, const uint32_t* a,
                                        uint32_t b0, uint32_t b1) {
    asm volatile(
        "mma.sync.aligned.m16n8k16.row.col.f32.f16.f16.f32 "
        "{%0,%1,%2,%3}, {%4,%5,%6,%7}, {%8,%9}, {%0,%1,%2,%3};"
        : "+f"(c[0]), "+f"(c[1]), "+f"(c[2]), "+f"(c[3])
        : "r"(a[0]), "r"(a[1]), "r"(a[2]), "r"(a[3]), "r"(b0), "r"(b1));
}

// ---------------- GEMM tile (device) ----------------
// [128,128] tile at (rowBase,colBase) of D[M,4096] = A[M,K] @ BT[4096,K]^T
// 16 warps: warpM = wid&3 (rows), warpN = wid>>2 (cols); warp tile 32x32.
// MODE 0: OutF = acc (fp32)                                   (c0)
// MODE 1: v = clip(0.5*Sold + C0q + 0.25*acc)                 (s1; C0q = 0.25*c0)
// MODE 2: v = clip(0.5*Sold + 0.25*(acc + s3old@bw2))         (s2)
// FINAL=false: OutH = h(v);  FINAL=true: fOut[row*OUTW + fColOff + col] = v (fp32)
template <int MODE, bool FINAL>
__device__ __forceinline__ void gemm_tile(
    const __half* __restrict__ A, const __half* __restrict__ BT, int K,
    float* __restrict__ OutF, __half* __restrict__ OutH,
    const __half* __restrict__ Sold, const __half* __restrict__ C0q,
    const float* __restrict__ s3old, const float* __restrict__ bw2,
    float* __restrict__ fOut, int fColOff,
    int rowBase, int colBase, __half* smem)
{
    const int tid  = threadIdx.x;
    const int lane = tid & 31;
    const int wid  = tid >> 5;              // 0..15
    const int g = lane >> 2, q = lane & 3;
    const int warpM = wid & 3;              // 4 row-groups of 32
    const int warpN = wid >> 2;             // 4 col-groups of 32

    float acc[2][4][4];
#pragma unroll
    for (int mi = 0; mi < 2; mi++)
#pragma unroll
        for (int ni = 0; ni < 4; ni++)
#pragma unroll
            for (int t = 0; t < 4; t++) acc[mi][ni][t] = 0.0f;

    // loaders: 512 threads, row = tid>>2, 2 of 8 16B-segments each for A and B
    const int ldr  = tid >> 2;              // 0..127
    const int seg0 = (tid & 3) * 2;         // 0,2,4,6

    const __half* Ag = A  + (size_t)(rowBase + ldr) * K;
    const __half* Bg = BT + (size_t)(colBase + ldr) * K;

    const int nIt = K / BKK;

#define LOAD_STAGE(s, kt)                                            \
    do {                                                             \
        __half* As_ = smem + (s) * STAGE_HALFS;                      \
        __half* Bs_ = As_ + 128 * ROWH;                              \
        uint32_t dA = smem_u32(As_ + ldr * ROWH);                    \
        uint32_t dB = smem_u32(Bs_ + ldr * ROWH);                    \
        _Pragma("unroll")                                            \
        for (int u = 0; u < 2; u++) {                                \
            int sg = seg0 + u;                                       \
            cp16(dA + sg * 16, Ag + (kt) + sg * 8);                  \
            cp16(dB + sg * 16, Bg + (kt) + sg * 8);                  \
        }                                                            \
    } while (0)

    LOAD_STAGE(0, 0);       CP_COMMIT();
    LOAD_STAGE(1, BKK);     CP_COMMIT();
    LOAD_STAGE(2, 2 * BKK); CP_COMMIT();

    const int lrow = (lane & 7) + ((lane >> 3) & 1) * 8;
    const int lcolB = ((lane >> 4) & 1) * 16;   // bytes

    uint32_t a[2][2][4];   // [buf][mi][frag]
    uint32_t b[2][2][4];   // [buf][nj][frag]

#define LOAD_FRAGS(buf, aB, bB, ko)                                          \
    do {                                                                     \
        _Pragma("unroll")                                                    \
        for (int mi = 0; mi < 2; mi++)                                       \
            ldsm4(a[buf][mi][0], a[buf][mi][1], a[buf][mi][2], a[buf][mi][3],\
                  (aB) + mi * 16 * (ROWH * 2) + (ko));                       \
        _Pragma("unroll")                                                    \
        for (int nj = 0; nj < 2; nj++)                                       \
            ldsm4(b[buf][nj][0], b[buf][nj][1], b[buf][nj][2], b[buf][nj][3],\
                  (bB) + nj * 16 * (ROWH * 2) + (ko));                       \
    } while (0)

#define DO_MMA(buf)                                                          \
    do {                                                                     \
        _Pragma("unroll")                                                    \
        for (int nj = 0; nj < 2; nj++) {                                     \
            _Pragma("unroll")                                                \
            for (int mi = 0; mi < 2; mi++) {                                 \
                mma_f16(acc[mi][nj * 2 + 0], a[buf][mi],                     \
                        b[buf][nj][0], b[buf][nj][2]);                       \
                mma_f16(acc[mi][nj * 2 + 1], a[buf][mi],                     \
                        b[buf][nj][1], b[buf][nj][3]);                       \
            }                                                                \
        }                                                                    \
    } while (0)

    // prime: wait for stage 0, load its first k-step fragments
    CP_WAIT(2);
    __syncthreads();
    {
        const __half* As = smem;
        const __half* Bs = As + 128 * ROWH;
        const uint32_t aB = smem_u32(As + (warpM * 32 + lrow) * ROWH) + lcolB;
        const uint32_t bB = smem_u32(Bs + (warpN * 32 + lrow) * ROWH) + lcolB;
        LOAD_FRAGS(0, aB, bB, 0);
    }

    for (int it = 0; it < nIt; ++it) {
        if (it + 3 < nIt) {
            LOAD_STAGE((it + 3) & (NSTAGE - 1), (it + 3) * BKK);
        }
        CP_COMMIT();

        const __half* As = smem + (it & (NSTAGE - 1)) * STAGE_HALFS;
        const __half* Bs = As + 128 * ROWH;
        const uint32_t aB = smem_u32(As + (warpM * 32 + lrow) * ROWH) + lcolB;
        const uint32_t bB = smem_u32(Bs + (warpN * 32 + lrow) * ROWH) + lcolB;

        // k-steps 0..2: prefetch ks+1 into other buffer, then mma current
#pragma unroll
        for (int ks = 0; ks < 3; ks++) {
            LOAD_FRAGS((ks + 1) & 1, aB, bB, (ks + 1) * 32);
            DO_MMA(ks & 1);
        }

        // boundary: advance smem pipeline, prefetch next stage's k-step 0
        if (it + 1 < nIt) {
            CP_WAIT(2);
            __syncthreads();
            const __half* As2 = smem + ((it + 1) & (NSTAGE - 1)) * STAGE_HALFS;
            const __half* Bs2 = As2 + 128 * ROWH;
            const uint32_t aB2 = smem_u32(As2 + (warpM * 32 + lrow) * ROWH) + lcolB;
            const uint32_t bB2 = smem_u32(Bs2 + (warpN * 32 + lrow) * ROWH) + lcolB;
            LOAD_FRAGS(0, aB2, bB2, 0);
        }
        DO_MMA(1);   // k-step 3 lives in buffer 1
    }
#undef LOAD_FRAGS
#undef DO_MMA
#undef LOAD_STAGE

    // ---------------- epilogue ----------------
    const int rw = rowBase + warpM * 32;
    const int cw = colBase + warpN * 32;

    if (MODE == 2) {
        float s3r[2][2][10];
#pragma unroll
        for (int mi = 0; mi < 2; mi++)
#pragma unroll
            for (int h = 0; h < 2; h++) {
                const int r = rw + mi * 16 + h * 8 + g;
#pragma unroll
                for (int k = 0; k < NOUT; k++)
                    s3r[mi][h][k] = s3old[r * NOUT + k];
            }
#pragma unroll
        for (int ni = 0; ni < 4; ni++) {
            const int cb = cw + ni * 8 + q * 2;
#pragma unroll
            for (int k = 0; k < NOUT; k++) {
                const float2 b2 = *(const float2*)&bw2[(size_t)k * HID + cb];
#pragma unroll
                for (int mi = 0; mi < 2; mi++) {
                    acc[mi][ni][0] = fmaf(s3r[mi][0][k], b2.x, acc[mi][ni][0]);
                    acc[mi][ni][1] = fmaf(s3r[mi][0][k], b2.y, acc[mi][ni][1]);
                    acc[mi][ni][2] = fmaf(s3r[mi][1][k], b2.x, acc[mi][ni][2]);
                    acc[mi][ni][3] = fmaf(s3r[mi][1][k], b2.y, acc[mi][ni][3]);
                }
            }
        }
    }

#pragma unroll
    for (int mi = 0; mi < 2; mi++) {
#pragma unroll
        for (int ni = 0; ni < 4; ni++) {
            const int r0 = rw + mi * 16 + g;
            const int cb = cw + ni * 8 + q * 2;
#pragma unroll
            for (int h = 0; h < 2; h++) {
                const int row = r0 + h * 8;
                const size_t idx = (size_t)row * HID + cb;
                float vx = acc[mi][ni][h * 2 + 0];
                float vy = acc[mi][ni][h * 2 + 1];
                if (MODE == 0) {
                    *(float2*)&OutF[idx] = make_float2(vx, vy);
                } else {
                    const float2 so = __half22float2(*(const __half2*)&Sold[idx]);
                    if (MODE == 1) {
                        const float2 c2 = __half22float2(*(const __half2*)&C0q[idx]);
                        vx = 0.5f * so.x + c2.x + 0.25f * vx;
                        vy = 0.5f * so.y + c2.y + 0.25f * vy;
                    } else {
                        vx = 0.5f * so.x + 0.25f * vx;
                        vy = 0.5f * so.y + 0.25f * vy;
                    }
                    vx = fminf(fmaxf(vx, 0.0f), 1.0f);
                    vy = fminf(fmaxf(vy, 0.0f), 1.0f);
                    if (FINAL) {
                        *(float2*)&fOut[(size_t)row * OUTW + fColOff + cb] =
                            make_float2(vx, vy);
                    } else {
                        *(__half2*)&OutH[idx] = __floats2half2_rn(vx, vy);
                    }
                }
            }
        }
    }
}

// ---------------- s3 tile (device): 32 rows, 512 threads ----------------
template <bool FINAL>
__device__ __forceinline__ void s3_tile(
    const __half* __restrict__ s2old, const float* __restrict__ fw2,
    const float* __restrict__ s3old, const float* __restrict__ y,
    float* __restrict__ s3new, float* __restrict__ fOut,
    int weak, int rowBase, __half* smem_raw)
{
    const int tid = threadIdx.x, lane = tid & 31, wid = tid >> 5;   // 16 warps
    float* fs = (float*)smem_raw;
    float acc[2][NOUT];
#pragma unroll
    for (int r = 0; r < 2; r++)
#pragma unroll
        for (int j = 0; j < NOUT; j++) acc[r][j] = 0.0f;

    for (int c = 0; c < 8; c++) {
        __syncthreads();
        for (int i = tid; i < 512 * NOUT; i += NTHREADS) {
            int kl = i / NOUT, j = i - kl * NOUT;
            fs[kl * 11 + j] = fw2[(size_t)(c * 512 + kl) * NOUT + j];
        }
        __syncthreads();
#pragma unroll
        for (int r = 0; r < 2; r++) {
            const int row = rowBase + wid * 2 + r;
            const __half* s2r = s2old + (size_t)row * HID + c * 512;
#pragma unroll 4
            for (int i = 0; i < 16; i++) {
                const int kl = lane + i * 32;
                const float sv = __half2float(s2r[kl]);
#pragma unroll
                for (int j = 0; j < NOUT; j++)
                    acc[r][j] = fmaf(sv, fs[kl * 11 + j], acc[r][j]);
            }
        }
    }

#pragma unroll
    for (int r = 0; r < 2; r++) {
        const int row = rowBase + wid * 2 + r;
#pragma unroll
        for (int j = 0; j < NOUT; j++) {
            float v = acc[r][j];
#pragma unroll
            for (int o = 16; o; o >>= 1) v += __shfl_xor_sync(0xffffffffu, v, o);
            if (lane == 0) {
                float out = weak ? 0.5f * (v + y[row * NOUT + j])
                                 : 0.5f * (s3old[row * NOUT + j] + v);
                out = fminf(fmaxf(out, 0.0f), 1.0f);
                if (FINAL) fOut[(size_t)row * OUTW + 2 * HID + j] = out;
                else       s3new[row * NOUT + j] = out;
            }
        }
    }
}

// ---------------- fused step kernel: 136 CTAs = one wave ----------------
template <bool FINAL>
__global__ __launch_bounds__(NTHREADS, 1) void step_kernel(
    const __half* __restrict__ s1old, const __half* __restrict__ s2old,
    const float* __restrict__ s3old,
    __half* __restrict__ s1new, __half* __restrict__ s2new, float* __restrict__ s3new,
    const __half* __restrict__ fw1T, const __half* __restrict__ bw1T,
    const float* __restrict__ bw2, const float* __restrict__ fw2,
    const __half* __restrict__ c0q, const float* __restrict__ y,
    float* __restrict__ fOut, int weak)
{
    extern __shared__ __half smem[];
    const int bid = blockIdx.x;
    if (bid < 64) {
        gemm_tile<1, FINAL>(s2old, bw1T, HID, nullptr, s1new, s1old, c0q, nullptr,
                            nullptr, fOut, 0,
                            (bid >> 5) * 128, (bid & 31) * 128, smem);
    } else if (bid < 128) {
        const int t = bid - 64;
        gemm_tile<2, FINAL>(s1old, fw1T, HID, nullptr, s2new, s2old, nullptr, s3old,
                            bw2, fOut, HID,
                            (t >> 5) * 128, (t & 31) * 128, smem);
    } else {
        s3_tile<FINAL>(s2old, fw2, s3old, y, s3new, fOut, weak, (bid - 128) * 32, smem);
    }
}

__global__ __launch_bounds__(NTHREADS, 1) void c0_kernel(
    const __half* __restrict__ rx, const __half* __restrict__ fw0T,
    float* __restrict__ c0)
{
    extern __shared__ __half smem[];
    const int bid = blockIdx.x;
    gemm_tile<0, false>(rx, fw0T, NIN, c0, nullptr, nullptr, nullptr, nullptr,
                        nullptr, nullptr, 0,
                        (bid >> 5) * 128, (bid & 31) * 128, smem);
}

// ---------------- small kernels ----------------
__global__ void clip_kernel(const float* __restrict__ x, __half* __restrict__ rx, int n) {
    int i = blockIdx.x * blockDim.x + threadIdx.x;
    if (i < n) rx[i] = __float2half_rn(fminf(fmaxf(x[i], 0.0f), 1.0f));
}

__global__ void init_kernel(const float* __restrict__ c0, __half* __restrict__ c0q,
                            __half* __restrict__ s1, __half* __restrict__ s2,
                            float* __restrict__ s3) {
    int i = blockIdx.x * blockDim.x + threadIdx.x;
    if (i < BSZ * HID) {
        float qc = 0.25f * c0[i];
        c0q[i] = __float2half_rn(qc);
        s1[i] = __float2half_rn(fminf(fmaxf(qc, 0.0f), 1.0f));
        s2[i] = __half(0.0f);
    }
    if (i < BSZ * NOUT) s3[i] = 0.0f;
}

// 64x64-tile transpose+convert: dst[c][r] = h(src[r][c]); full-width fp16 stores.
__global__ void transpose64_kernel(const float* __restrict__ src,
                                   __half* __restrict__ dst, int R, int C) {
    __shared__ float tile[64][65];
    const int bx = blockIdx.x * 64;
    const int by = blockIdx.y * 64;
    const int tx = threadIdx.x, ty = threadIdx.y;
#pragma unroll
    for (int j = 0; j < 2; j++)
#pragma unroll
        for (int i = 0; i < 8; i++)
            tile[ty + i * 8][tx + j * 32] =
                src[(size_t)(by + ty + i * 8) * C + bx + tx + j * 32];
    __syncthreads();
#pragma unroll
    for (int i = 0; i < 8; i++) {
        const int cc = bx + ty + i * 8;
        const int k = ty + i * 8;
        __half2 v = __floats2half2_rn(tile[tx * 2][k], tile[tx * 2 + 1][k]);
        *(__half2*)&dst[(size_t)cc * R + by + tx * 2] = v;
    }
}

// ---------------- launch ----------------
extern "C" void kernel_launch(void* const* d_in, const int* in_sizes, int n_in,
                              void* d_out, int out_size)
{
    const float* x   = (const float*)d_in[0];
    const float* fw0 = (const float*)d_in[1];
    const float* fw1 = (const float*)d_in[2];
    const float* fw2 = (const float*)d_in[3];
    // d_in[4] = bw0 (unused by the dynamics)
    const float* bw1 = (const float*)d_in[5];
    const float* bw2 = (const float*)d_in[6];
    const float* y   = (const float*)d_in[7];
    float* out = (float*)d_out;

    cudaFuncSetAttribute(step_kernel<false>, cudaFuncAttributeMaxDynamicSharedMemorySize, SMEM_BYTES);
    cudaFuncSetAttribute(step_kernel<true>,  cudaFuncAttributeMaxDynamicSharedMemorySize, SMEM_BYTES);
    cudaFuncSetAttribute(c0_kernel,          cudaFuncAttributeMaxDynamicSharedMemorySize, SMEM_BYTES);

    __half *rx, *c0q, *s1base, *s2base, *fw0T, *fw1T, *bw1T;
    float *c0, *s3base;
    cudaGetSymbolAddress((void**)&rx, g_rx);
    cudaGetSymbolAddress((void**)&c0, g_c0);
    cudaGetSymbolAddress((void**)&c0q, g_c0q);
    cudaGetSymbolAddress((void**)&s1base, g_s1);
    cudaGetSymbolAddress((void**)&s2base, g_s2);
    cudaGetSymbolAddress((void**)&s3base, g_s3);
    cudaGetSymbolAddress((void**)&fw0T, g_fw0T);
    cudaGetSymbolAddress((void**)&fw1T, g_fw1T);
    cudaGetSymbolAddress((void**)&bw1T, g_bw1T);

    __half* s1p[2] = { s1base, s1base + (size_t)BSZ * HID };
    __half* s2p[2] = { s2base, s2base + (size_t)BSZ * HID };
    float*  s3p[2] = { s3base, s3base + (size_t)BSZ * NOUT };

    {
        dim3 blk(32, 8);
        transpose64_kernel<<<dim3(HID / 64, NIN / 64), blk>>>(fw0, fw0T, NIN, HID);
        transpose64_kernel<<<dim3(HID / 64, HID / 64), blk>>>(fw1, fw1T, HID, HID);
        transpose64_kernel<<<dim3(HID / 64, HID / 64), blk>>>(bw1, bw1T, HID, HID);
    }

    clip_kernel<<<(BSZ * NIN + 255) / 256, 256>>>(x, rx, BSZ * NIN);

    // c0 = rx @ fw0 (loop-invariant), fp32 output
    c0_kernel<<<64, NTHREADS, SMEM_BYTES>>>(rx, fw0T, c0);

    // step 0 collapses to elementwise (states start at zero)
    init_kernel<<<(BSZ * HID + 255) / 256, 256>>>(c0, c0q, s1p[1], s2p[1], s3p[1]);

    // steps 1..23 write fp16 state buffers
    for (int t = 1; t < STEPS_TOTAL - 1; t++) {
        const int p = t & 1;
        const int q = 1 - p;
        const int weak = (t >= STEPS_FREE) ? 1 : 0;
        step_kernel<false><<<136, NTHREADS, SMEM_BYTES>>>(
            s1p[p], s2p[p], s3p[p],
            s1p[q], s2p[q], s3p[q],
            fw1T, bw1T, bw2, fw2, c0q, y, nullptr, weak);
    }

    // final step (t = 24) writes fp32 results directly into d_out
    {
        const int t = STEPS_TOTAL - 1;   // 24
        const int p = t & 1;             // 0
        const int q = 1 - p;
        step_kernel<true><<<136, NTHREADS, SMEM_BYTES>>>(
            s1p[p], s2p[p], s3p[p],
            s1p[q], s2p[q], s3p[q],
            fw1T, bw1T, bw2, fw2, c0q, y, out, 1);
    }
}